// round 3
// baseline (speedup 1.0000x reference)
#include <cuda_runtime.h>
#include <cuda_bf16.h>
#include <math.h>

#define NNODES 50000
#define EMAXE  800000
#define IN_F   256
#define HH     4
#define DD     64
#define HD     256
#define HD2    512
#define NEG_SLOPE 0.2f

// ---------------- scratch (static __device__, no allocs) ----------------
__device__ float    g_feat1[NNODES * HD];
__device__ float    g_feat2[NNODES * HD];
__device__ float    g_sem  [NNODES * HD2];
__device__ float    g_el1[NNODES * HH], g_er1[NNODES * HH];
__device__ float    g_el2[NNODES * HH], g_er2[NNODES * HH];
__device__ unsigned g_emax1[NNODES * HH], g_emax2[NNODES * HH];
__device__ float    g_den1[NNODES * HH], g_den2[NNODES * HH];
__device__ float    g_eb1[EMAXE * HH], g_eb2[EMAXE * HH];

// monotone float<->uint mapping for atomicMax on floats (any sign)
__device__ __forceinline__ unsigned enc_f(float f) {
    unsigned u = __float_as_uint(f);
    return (u & 0x80000000u) ? ~u : (u | 0x80000000u);
}
__device__ __forceinline__ float dec_f(unsigned e) {
    unsigned u = (e & 0x80000000u) ? (e ^ 0x80000000u) : ~e;
    return __uint_as_float(u);
}

// ---------------- generic fp32 GEMM: C[m, n] = sum_k A[m,k]*B[n,k] (+bias[n]) ----
#define BM 128
#define BN 128
#define BK 16

__global__ void gemm_tn_kernel(const float* __restrict__ A, int lda,
                               const float* __restrict__ B, int ldb,   // B is [Nc x K] row-major
                               float* __restrict__ C, int ldc,
                               const float* __restrict__ bias,
                               int M, int Nc, int K)
{
    __shared__ float As[BK][BM + 4];
    __shared__ float Bs[BK][BN + 4];

    const int tid = threadIdx.x;           // 256 threads
    const int block_m = blockIdx.y * BM;
    const int block_n = blockIdx.x * BN;
    const int tx = tid & 15;               // 0..15
    const int ty = tid >> 4;               // 0..15

    float acc[8][8];
#pragma unroll
    for (int i = 0; i < 8; i++)
#pragma unroll
        for (int j = 0; j < 8; j++) acc[i][j] = 0.f;

    const int arow = tid >> 2;             // 0..63
    const int acol = (tid & 3) * 4;        // 0,4,8,12

    for (int k0 = 0; k0 < K; k0 += BK) {
#pragma unroll
        for (int i = 0; i < 2; i++) {
            int m = block_m + arow + i * 64;
            float4 v = make_float4(0.f, 0.f, 0.f, 0.f);
            if (m < M) v = *(const float4*)(A + (size_t)m * lda + k0 + acol);
            As[acol + 0][arow + i * 64] = v.x;
            As[acol + 1][arow + i * 64] = v.y;
            As[acol + 2][arow + i * 64] = v.z;
            As[acol + 3][arow + i * 64] = v.w;
        }
#pragma unroll
        for (int i = 0; i < 2; i++) {
            int n = block_n + arow + i * 64;
            float4 v = make_float4(0.f, 0.f, 0.f, 0.f);
            if (n < Nc) v = *(const float4*)(B + (size_t)n * ldb + k0 + acol);
            Bs[acol + 0][arow + i * 64] = v.x;
            Bs[acol + 1][arow + i * 64] = v.y;
            Bs[acol + 2][arow + i * 64] = v.z;
            Bs[acol + 3][arow + i * 64] = v.w;
        }
        __syncthreads();

#pragma unroll
        for (int kk = 0; kk < BK; kk++) {
            float a[8], b[8];
#pragma unroll
            for (int i = 0; i < 8; i++) a[i] = As[kk][ty * 8 + i];
#pragma unroll
            for (int j = 0; j < 8; j++) b[j] = Bs[kk][tx * 8 + j];
#pragma unroll
            for (int i = 0; i < 8; i++)
#pragma unroll
                for (int j = 0; j < 8; j++) acc[i][j] = fmaf(a[i], b[j], acc[i][j]);
        }
        __syncthreads();
    }

#pragma unroll
    for (int i = 0; i < 8; i++) {
        int m = block_m + ty * 8 + i;
        if (m >= M) continue;
#pragma unroll
        for (int j = 0; j < 8; j++) {
            int n = block_n + tx * 8 + j;
            if (n < Nc) {
                float v = acc[i][j];
                if (bias) v += bias[n];
                C[(size_t)m * ldc + n] = v;
            }
        }
    }
}

// ---------------- el/er: warp per (node, head) dot over D=64 ----------------
__global__ void elr_kernel(const float* __restrict__ feat,
                           const float* __restrict__ al, const float* __restrict__ ar,
                           float* __restrict__ el, float* __restrict__ er, int Nn)
{
    int w = (blockIdx.x * blockDim.x + threadIdx.x) >> 5;
    int lane = threadIdx.x & 31;
    if (w >= Nn * HH) return;
    int n = w / HH, hh = w % HH;
    const float2* f = (const float2*)(feat + (size_t)n * HD + hh * DD);
    const float2* a = (const float2*)(al + hh * DD);
    const float2* r = (const float2*)(ar + hh * DD);
    float2 fv = f[lane], av = a[lane], rv = r[lane];
    float sl = fv.x * av.x + fv.y * av.y;
    float sr = fv.x * rv.x + fv.y * rv.y;
#pragma unroll
    for (int o = 16; o; o >>= 1) {
        sl += __shfl_xor_sync(0xffffffffu, sl, o);
        sr += __shfl_xor_sync(0xffffffffu, sr, o);
    }
    if (lane == 0) { el[n * HH + hh] = sl; er[n * HH + hh] = sr; }
}

// ---------------- init: emax/den stats + bias-initialized sem ----------------
__global__ void init_stats_kernel(int Nn)
{
    int i = blockIdx.x * blockDim.x + threadIdx.x;
    if (i >= Nn * HH) return;
    g_emax1[i] = 0u; g_emax2[i] = 0u;
    g_den1[i] = 0.f; g_den2[i] = 0.f;
}

__global__ void init_sem_kernel(const float* __restrict__ b1,
                                const float* __restrict__ b2, int Nn)
{
    int i = blockIdx.x * blockDim.x + threadIdx.x;
    if (i >= Nn * HD2) return;
    int c = i & (HD2 - 1);
    g_sem[i] = (c < HD) ? b1[c] : b2[c - HD];
}

// ---------------- edge pass 1: e = leaky(el[src]+er[dst]); atomicMax ----------
__global__ void edge_pass1_kernel(const int* __restrict__ src, const int* __restrict__ dst,
                                  const float* __restrict__ el, const float* __restrict__ er,
                                  float* __restrict__ ebuf, unsigned* __restrict__ emax, int E)
{
    int e = blockIdx.x * blockDim.x + threadIdx.x;
    if (e >= E) return;
    int s = src[e], t = dst[e];
    float4 l = *(const float4*)(el + s * HH);
    float4 r = *(const float4*)(er + t * HH);
    float4 v;
    v.x = l.x + r.x; v.x = v.x > 0.f ? v.x : NEG_SLOPE * v.x;
    v.y = l.y + r.y; v.y = v.y > 0.f ? v.y : NEG_SLOPE * v.y;
    v.z = l.z + r.z; v.z = v.z > 0.f ? v.z : NEG_SLOPE * v.z;
    v.w = l.w + r.w; v.w = v.w > 0.f ? v.w : NEG_SLOPE * v.w;
    *(float4*)(ebuf + (size_t)e * HH) = v;
    atomicMax(&emax[t * HH + 0], enc_f(v.x));
    atomicMax(&emax[t * HH + 1], enc_f(v.y));
    atomicMax(&emax[t * HH + 2], enc_f(v.z));
    atomicMax(&emax[t * HH + 3], enc_f(v.w));
}

// ---------------- edge pass 2: ex = exp(e - emax[dst]); atomicAdd denom -------
__global__ void edge_pass2_kernel(const int* __restrict__ dst,
                                  float* __restrict__ ebuf,
                                  const unsigned* __restrict__ emax,
                                  float* __restrict__ den, int E)
{
    int e = blockIdx.x * blockDim.x + threadIdx.x;
    if (e >= E) return;
    int t = dst[e];
    float4 v = *(const float4*)(ebuf + (size_t)e * HH);
    uint4 m = *(const uint4*)(emax + t * HH);
    v.x = __expf(v.x - dec_f(m.x));
    v.y = __expf(v.y - dec_f(m.y));
    v.z = __expf(v.z - dec_f(m.z));
    v.w = __expf(v.w - dec_f(m.w));
    *(float4*)(ebuf + (size_t)e * HH) = v;
    atomicAdd(&den[t * HH + 0], v.x);
    atomicAdd(&den[t * HH + 1], v.y);
    atomicAdd(&den[t * HH + 2], v.z);
    atomicAdd(&den[t * HH + 3], v.w);
}

// ---------------- edge pass 3: warp/edge scatter feat[src]*alpha into sem -----
__global__ void edge_pass3_kernel(const int* __restrict__ src, const int* __restrict__ dst,
                                  const float* __restrict__ ebuf,
                                  const float* __restrict__ den,
                                  const float* __restrict__ feat,
                                  int rel_off, int E)
{
    int gw = (blockIdx.x * blockDim.x + threadIdx.x) >> 5;
    int lane = threadIdx.x & 31;
    if (gw >= E) return;
    int s = src[gw], t = dst[gw];
    float alpha = 0.f;
    if (lane < HH) alpha = ebuf[(size_t)gw * HH + lane] / den[t * HH + lane];
    alpha = __shfl_sync(0xffffffffu, alpha, lane >> 3);   // 8 lanes per head
    const float4* fp = (const float4*)(feat + (size_t)s * HD);
    float4 a = fp[lane * 2 + 0];
    float4 b = fp[lane * 2 + 1];
    float* o = g_sem + (size_t)t * HD2 + rel_off + lane * 8;
    atomicAdd(o + 0, a.x * alpha);
    atomicAdd(o + 1, a.y * alpha);
    atomicAdd(o + 2, a.z * alpha);
    atomicAdd(o + 3, a.w * alpha);
    atomicAdd(o + 4, b.x * alpha);
    atomicAdd(o + 5, b.y * alpha);
    atomicAdd(o + 6, b.z * alpha);
    atomicAdd(o + 7, b.w * alpha);
}

// ---------------- launch ----------------
static inline int ceil_div(int a, int b) { return (a + b - 1) / b; }

extern "C" void kernel_launch(void* const* d_in, const int* in_sizes, int n_in,
                              void* d_out, int out_size)
{
    const float* h    = (const float*)d_in[0];
    const float* Wg1  = (const float*)d_in[1];
    const float* al1  = (const float*)d_in[2];
    const float* ar1  = (const float*)d_in[3];
    const float* b1   = (const float*)d_in[4];
    const float* Wg2  = (const float*)d_in[5];
    const float* al2  = (const float*)d_in[6];
    const float* ar2  = (const float*)d_in[7];
    const float* b2   = (const float*)d_in[8];
    const float* Wfc  = (const float*)d_in[9];
    const float* bfc  = (const float*)d_in[10];
    const int*   src1 = (const int*)d_in[11];
    const int*   dst1 = (const int*)d_in[12];
    const int*   src2 = (const int*)d_in[13];
    const int*   dst2 = (const int*)d_in[14];
    float* out = (float*)d_out;

    const int Nn = in_sizes[0] / IN_F;
    const int E1 = in_sizes[11];
    const int E2 = in_sizes[13];

    float *feat1, *feat2, *sem, *el1, *er1, *el2, *er2, *den1, *den2, *eb1, *eb2;
    unsigned *emax1, *emax2;
    cudaGetSymbolAddress((void**)&feat1, g_feat1);
    cudaGetSymbolAddress((void**)&feat2, g_feat2);
    cudaGetSymbolAddress((void**)&sem,   g_sem);
    cudaGetSymbolAddress((void**)&el1,   g_el1);
    cudaGetSymbolAddress((void**)&er1,   g_er1);
    cudaGetSymbolAddress((void**)&el2,   g_el2);
    cudaGetSymbolAddress((void**)&er2,   g_er2);
    cudaGetSymbolAddress((void**)&emax1, g_emax1);
    cudaGetSymbolAddress((void**)&emax2, g_emax2);
    cudaGetSymbolAddress((void**)&den1,  g_den1);
    cudaGetSymbolAddress((void**)&den2,  g_den2);
    cudaGetSymbolAddress((void**)&eb1,   g_eb1);
    cudaGetSymbolAddress((void**)&eb2,   g_eb2);

    // 1) projections
    {
        dim3 grid(ceil_div(HD, BN), ceil_div(Nn, BM));
        gemm_tn_kernel<<<grid, 256>>>(h, IN_F, Wg1, IN_F, feat1, HD, nullptr, Nn, HD, IN_F);
        gemm_tn_kernel<<<grid, 256>>>(h, IN_F, Wg2, IN_F, feat2, HD, nullptr, Nn, HD, IN_F);
    }
    // 2) el / er
    {
        int warps = Nn * HH;
        int grid = ceil_div(warps * 32, 256);
        elr_kernel<<<grid, 256>>>(feat1, al1, ar1, el1, er1, Nn);
        elr_kernel<<<grid, 256>>>(feat2, al2, ar2, el2, er2, Nn);
    }
    // 3) init stats + sem
    init_stats_kernel<<<ceil_div(Nn * HH, 256), 256>>>(Nn);
    init_sem_kernel<<<ceil_div(Nn * HD2, 256), 256>>>(b1, b2, Nn);

    // 4) edge softmax passes
    edge_pass1_kernel<<<ceil_div(E1, 256), 256>>>(src1, dst1, el1, er1, eb1, emax1, E1);
    edge_pass1_kernel<<<ceil_div(E2, 256), 256>>>(src2, dst2, el2, er2, eb2, emax2, E2);
    edge_pass2_kernel<<<ceil_div(E1, 256), 256>>>(dst1, eb1, emax1, den1, E1);
    edge_pass2_kernel<<<ceil_div(E2, 256), 256>>>(dst2, eb2, emax2, den2, E2);
    edge_pass3_kernel<<<ceil_div(E1 * 32, 256), 256>>>(src1, dst1, eb1, den1, feat1, 0,  E1);
    edge_pass3_kernel<<<ceil_div(E2 * 32, 256), 256>>>(src2, dst2, eb2, den2, feat2, HD, E2);

    // 5) FC
    {
        dim3 grid(ceil_div(HD, BN), ceil_div(Nn, BM));
        gemm_tn_kernel<<<grid, 256>>>(sem, HD2, Wfc, HD2, out, HD, bfc, Nn, HD, HD2);
    }
}

// round 5
// speedup vs baseline: 2.4675x; 2.4675x over previous
#include <cuda_runtime.h>
#include <cuda_bf16.h>
#include <math.h>

#define NNODES 50000
#define EMAXE  800000
#define IN_F   256
#define HH     4
#define DD     64
#define HD     256
#define HD2    512
#define NEG_SLOPE 0.2f

// ---------------- scratch (static __device__, no allocs) ----------------
__device__ __align__(16) float g_feat1[NNODES * HD];
__device__ __align__(16) float g_feat2[NNODES * HD];
__device__ __align__(16) float g_sem  [NNODES * HD2];
__device__ __align__(16) float g_el1[NNODES * HH], g_er1[NNODES * HH];
__device__ __align__(16) float g_el2[NNODES * HH], g_er2[NNODES * HH];

// CSR-by-dst scratch
__device__ int g_cnt1[NNODES],  g_cnt2[NNODES];
__device__ int g_off1[NNODES + 1], g_off2[NNODES + 1];
__device__ int g_cur1[NNODES],  g_cur2[NNODES];
__device__ int g_csr1[EMAXE],   g_csr2[EMAXE];

// ---------------- generic fp32 GEMM: C[m, n] = sum_k A[m,k]*B[n,k] (+bias[n]) ----
#define BM 128
#define BN 128
#define BK 16

__global__ void gemm_tn_kernel(const float* __restrict__ A, int lda,
                               const float* __restrict__ B, int ldb,   // B is [Nc x K] row-major
                               float* __restrict__ C, int ldc,
                               const float* __restrict__ bias,
                               int M, int Nc, int K)
{
    __shared__ float As[BK][BM + 4];
    __shared__ float Bs[BK][BN + 4];

    const int tid = threadIdx.x;           // 256 threads
    const int block_m = blockIdx.y * BM;
    const int block_n = blockIdx.x * BN;
    const int tx = tid & 15;               // 0..15
    const int ty = tid >> 4;               // 0..15

    float acc[8][8];
#pragma unroll
    for (int i = 0; i < 8; i++)
#pragma unroll
        for (int j = 0; j < 8; j++) acc[i][j] = 0.f;

    const int arow = tid >> 2;             // 0..63
    const int acol = (tid & 3) * 4;        // 0,4,8,12

    for (int k0 = 0; k0 < K; k0 += BK) {
#pragma unroll
        for (int i = 0; i < 2; i++) {
            int m = block_m + arow + i * 64;
            float4 v = make_float4(0.f, 0.f, 0.f, 0.f);
            if (m < M) v = *(const float4*)(A + (size_t)m * lda + k0 + acol);
            As[acol + 0][arow + i * 64] = v.x;
            As[acol + 1][arow + i * 64] = v.y;
            As[acol + 2][arow + i * 64] = v.z;
            As[acol + 3][arow + i * 64] = v.w;
        }
#pragma unroll
        for (int i = 0; i < 2; i++) {
            int n = block_n + arow + i * 64;
            float4 v = make_float4(0.f, 0.f, 0.f, 0.f);
            if (n < Nc) v = *(const float4*)(B + (size_t)n * ldb + k0 + acol);
            Bs[acol + 0][arow + i * 64] = v.x;
            Bs[acol + 1][arow + i * 64] = v.y;
            Bs[acol + 2][arow + i * 64] = v.z;
            Bs[acol + 3][arow + i * 64] = v.w;
        }
        __syncthreads();

#pragma unroll
        for (int kk = 0; kk < BK; kk++) {
            float a[8], b[8];
#pragma unroll
            for (int i = 0; i < 8; i++) a[i] = As[kk][ty * 8 + i];
#pragma unroll
            for (int j = 0; j < 8; j++) b[j] = Bs[kk][tx * 8 + j];
#pragma unroll
            for (int i = 0; i < 8; i++)
#pragma unroll
                for (int j = 0; j < 8; j++) acc[i][j] = fmaf(a[i], b[j], acc[i][j]);
        }
        __syncthreads();
    }

#pragma unroll
    for (int i = 0; i < 8; i++) {
        int m = block_m + ty * 8 + i;
        if (m >= M) continue;
#pragma unroll
        for (int j = 0; j < 8; j++) {
            int n = block_n + tx * 8 + j;
            if (n < Nc) {
                float v = acc[i][j];
                if (bias) v += bias[n];
                C[(size_t)m * ldc + n] = v;
            }
        }
    }
}

// ---------------- el/er: warp per (node, head) dot over D=64 ----------------
__global__ void elr_kernel(const float* __restrict__ feat,
                           const float* __restrict__ al, const float* __restrict__ ar,
                           float* __restrict__ el, float* __restrict__ er, int Nn)
{
    int w = (blockIdx.x * blockDim.x + threadIdx.x) >> 5;
    int lane = threadIdx.x & 31;
    if (w >= Nn * HH) return;
    int n = w / HH, hh = w % HH;
    const float2* f = (const float2*)(feat + (size_t)n * HD + hh * DD);
    const float2* a = (const float2*)(al + hh * DD);
    const float2* r = (const float2*)(ar + hh * DD);
    float2 fv = f[lane], av = a[lane], rv = r[lane];
    float sl = fv.x * av.x + fv.y * av.y;
    float sr = fv.x * rv.x + fv.y * rv.y;
#pragma unroll
    for (int o = 16; o; o >>= 1) {
        sl += __shfl_xor_sync(0xffffffffu, sl, o);
        sr += __shfl_xor_sync(0xffffffffu, sr, o);
    }
    if (lane == 0) { el[n * HH + hh] = sl; er[n * HH + hh] = sr; }
}

// ---------------- CSR build ----------------
__global__ void zero_cnt_kernel(int Nn)
{
    int i = blockIdx.x * blockDim.x + threadIdx.x;
    if (i < Nn) { g_cnt1[i] = 0; g_cnt2[i] = 0; }
}

__global__ void hist_kernel(const int* __restrict__ dst, int* __restrict__ cnt, int E)
{
    int e = blockIdx.x * blockDim.x + threadIdx.x;
    if (e < E) atomicAdd(&cnt[dst[e]], 1);
}

// single-block (1024 threads) exclusive scan: off[i], cursor[i]=off[i], off[Nn]=total
__global__ void scan_kernel(const int* __restrict__ cnt, int* __restrict__ off,
                            int* __restrict__ cursor, int Nn)
{
    __shared__ int part[1024];
    int tid = threadIdx.x;
    int per = (Nn + 1023) >> 10;
    int start = tid * per;
    int stop  = min(start + per, Nn);
    int sum = 0;
    for (int i = start; i < stop; i++) sum += cnt[i];
    part[tid] = sum;
    __syncthreads();
#pragma unroll
    for (int o = 1; o < 1024; o <<= 1) {
        int v = (tid >= o) ? part[tid - o] : 0;
        __syncthreads();
        part[tid] += v;
        __syncthreads();
    }
    int run = (tid > 0) ? part[tid - 1] : 0;
    for (int i = start; i < stop; i++) {
        off[i] = run; cursor[i] = run; run += cnt[i];
    }
    if (stop == Nn) off[Nn] = (tid > 0) ? part[1023] : run;
}

__global__ void fill_kernel(const int* __restrict__ src, const int* __restrict__ dst,
                            int* __restrict__ cursor, int* __restrict__ csr, int E)
{
    int e = blockIdx.x * blockDim.x + threadIdx.x;
    if (e >= E) return;
    int pos = atomicAdd(&cursor[dst[e]], 1);
    csr[pos] = src[e];
}

// ---------------- fused GAT aggregate: warp per dst node, no atomics ----------
__global__ void gat_aggregate_kernel(const int* __restrict__ off, const int* __restrict__ csr,
                                     const float* __restrict__ el, const float* __restrict__ er,
                                     const float* __restrict__ feat,
                                     const float* __restrict__ bias,
                                     int rel_off, int Nn)
{
    int n = (blockIdx.x * blockDim.x + threadIdx.x) >> 5;
    int lane = threadIdx.x & 31;
    if (n >= Nn) return;

    const int beg = off[n], end = off[n + 1];
    float4 er4 = *(const float4*)(er + n * HH);

    // phase 1: per-head max of leaky(el[src]+er[dst])
    float4 m = make_float4(-INFINITY, -INFINITY, -INFINITY, -INFINITY);
    for (int k = beg + lane; k < end; k += 32) {
        int s = csr[k];
        float4 l = *(const float4*)(el + s * HH);
        float4 e;
        e.x = l.x + er4.x; e.x = e.x > 0.f ? e.x : NEG_SLOPE * e.x;
        e.y = l.y + er4.y; e.y = e.y > 0.f ? e.y : NEG_SLOPE * e.y;
        e.z = l.z + er4.z; e.z = e.z > 0.f ? e.z : NEG_SLOPE * e.z;
        e.w = l.w + er4.w; e.w = e.w > 0.f ? e.w : NEG_SLOPE * e.w;
        m.x = fmaxf(m.x, e.x); m.y = fmaxf(m.y, e.y);
        m.z = fmaxf(m.z, e.z); m.w = fmaxf(m.w, e.w);
    }
#pragma unroll
    for (int o = 16; o; o >>= 1) {
        m.x = fmaxf(m.x, __shfl_xor_sync(0xffffffffu, m.x, o));
        m.y = fmaxf(m.y, __shfl_xor_sync(0xffffffffu, m.y, o));
        m.z = fmaxf(m.z, __shfl_xor_sync(0xffffffffu, m.z, o));
        m.w = fmaxf(m.w, __shfl_xor_sync(0xffffffffu, m.w, o));
    }

    // phase 2: per-head denom
    float4 ds = make_float4(0.f, 0.f, 0.f, 0.f);
    for (int k = beg + lane; k < end; k += 32) {
        int s = csr[k];
        float4 l = *(const float4*)(el + s * HH);
        float4 e;
        e.x = l.x + er4.x; e.x = e.x > 0.f ? e.x : NEG_SLOPE * e.x;
        e.y = l.y + er4.y; e.y = e.y > 0.f ? e.y : NEG_SLOPE * e.y;
        e.z = l.z + er4.z; e.z = e.z > 0.f ? e.z : NEG_SLOPE * e.z;
        e.w = l.w + er4.w; e.w = e.w > 0.f ? e.w : NEG_SLOPE * e.w;
        ds.x += __expf(e.x - m.x); ds.y += __expf(e.y - m.y);
        ds.z += __expf(e.z - m.z); ds.w += __expf(e.w - m.w);
    }
#pragma unroll
    for (int o = 16; o; o >>= 1) {
        ds.x += __shfl_xor_sync(0xffffffffu, ds.x, o);
        ds.y += __shfl_xor_sync(0xffffffffu, ds.y, o);
        ds.z += __shfl_xor_sync(0xffffffffu, ds.z, o);
        ds.w += __shfl_xor_sync(0xffffffffu, ds.w, o);
    }

    // phase 3: weighted gather. lane covers output cols [lane*8, lane*8+8), head = lane>>3
    const int head = lane >> 3;
    const float mh   = head == 0 ? m.x  : head == 1 ? m.y  : head == 2 ? m.z  : m.w;
    const float dh   = head == 0 ? ds.x : head == 1 ? ds.y : head == 2 ? ds.z : ds.w;
    const float erh  = head == 0 ? er4.x: head == 1 ? er4.y: head == 2 ? er4.z: er4.w;
    const float invd = 1.0f / dh;

    float acc[8];
#pragma unroll
    for (int i = 0; i < 8; i++) acc[i] = 0.f;

    for (int base = beg; base < end; base += 32) {
        int myidx = (base + lane < end) ? csr[base + lane] : 0;
        int cnt = min(32, end - base);
#pragma unroll 2
        for (int j = 0; j < cnt; j++) {
            int s = __shfl_sync(0xffffffffu, myidx, j);
            float e = el[s * HH + head] + erh;
            e = e > 0.f ? e : NEG_SLOPE * e;
            float alpha = __expf(e - mh) * invd;
            const float4* fp = (const float4*)(feat + (size_t)s * HD + lane * 8);
            float4 a = fp[0], b = fp[1];
            acc[0] = fmaf(a.x, alpha, acc[0]);
            acc[1] = fmaf(a.y, alpha, acc[1]);
            acc[2] = fmaf(a.z, alpha, acc[2]);
            acc[3] = fmaf(a.w, alpha, acc[3]);
            acc[4] = fmaf(b.x, alpha, acc[4]);
            acc[5] = fmaf(b.y, alpha, acc[5]);
            acc[6] = fmaf(b.z, alpha, acc[6]);
            acc[7] = fmaf(b.w, alpha, acc[7]);
        }
    }

    float4 bo0 = *(const float4*)(bias + lane * 8);
    float4 bo1 = *(const float4*)(bias + lane * 8 + 4);
    float* o = g_sem + (size_t)n * HD2 + rel_off + lane * 8;
    float4 w0 = make_float4(acc[0] + bo0.x, acc[1] + bo0.y, acc[2] + bo0.z, acc[3] + bo0.w);
    float4 w1 = make_float4(acc[4] + bo1.x, acc[5] + bo1.y, acc[6] + bo1.z, acc[7] + bo1.w);
    *(float4*)(o + 0) = w0;
    *(float4*)(o + 4) = w1;
}

// ---------------- launch ----------------
static inline int ceil_div(int a, int b) { return (a + b - 1) / b; }

extern "C" void kernel_launch(void* const* d_in, const int* in_sizes, int n_in,
                              void* d_out, int out_size)
{
    const float* h    = (const float*)d_in[0];
    const float* Wg1  = (const float*)d_in[1];
    const float* al1  = (const float*)d_in[2];
    const float* ar1  = (const float*)d_in[3];
    const float* b1   = (const float*)d_in[4];
    const float* Wg2  = (const float*)d_in[5];
    const float* al2  = (const float*)d_in[6];
    const float* ar2  = (const float*)d_in[7];
    const float* b2   = (const float*)d_in[8];
    const float* Wfc  = (const float*)d_in[9];
    const float* bfc  = (const float*)d_in[10];
    const int*   src1 = (const int*)d_in[11];
    const int*   dst1 = (const int*)d_in[12];
    const int*   src2 = (const int*)d_in[13];
    const int*   dst2 = (const int*)d_in[14];
    float* out = (float*)d_out;

    const int Nn = in_sizes[0] / IN_F;
    const int E1 = in_sizes[11];
    const int E2 = in_sizes[13];

    float *feat1, *feat2, *sem, *el1, *er1, *el2, *er2;
    int *cnt1, *cnt2, *off1, *off2, *cur1, *cur2, *csr1, *csr2;
    cudaGetSymbolAddress((void**)&feat1, g_feat1);
    cudaGetSymbolAddress((void**)&feat2, g_feat2);
    cudaGetSymbolAddress((void**)&sem,   g_sem);
    cudaGetSymbolAddress((void**)&el1,   g_el1);
    cudaGetSymbolAddress((void**)&er1,   g_er1);
    cudaGetSymbolAddress((void**)&el2,   g_el2);
    cudaGetSymbolAddress((void**)&er2,   g_er2);
    cudaGetSymbolAddress((void**)&cnt1,  g_cnt1);
    cudaGetSymbolAddress((void**)&cnt2,  g_cnt2);
    cudaGetSymbolAddress((void**)&off1,  g_off1);
    cudaGetSymbolAddress((void**)&off2,  g_off2);
    cudaGetSymbolAddress((void**)&cur1,  g_cur1);
    cudaGetSymbolAddress((void**)&cur2,  g_cur2);
    cudaGetSymbolAddress((void**)&csr1,  g_csr1);
    cudaGetSymbolAddress((void**)&csr2,  g_csr2);

    // CSR build (independent of GEMMs, issued first)
    zero_cnt_kernel<<<ceil_div(Nn, 256), 256>>>(Nn);
    hist_kernel<<<ceil_div(E1, 256), 256>>>(dst1, cnt1, E1);
    hist_kernel<<<ceil_div(E2, 256), 256>>>(dst2, cnt2, E2);
    scan_kernel<<<1, 1024>>>(cnt1, off1, cur1, Nn);
    scan_kernel<<<1, 1024>>>(cnt2, off2, cur2, Nn);
    fill_kernel<<<ceil_div(E1, 256), 256>>>(src1, dst1, cur1, csr1, E1);
    fill_kernel<<<ceil_div(E2, 256), 256>>>(src2, dst2, cur2, csr2, E2);

    // projections
    {
        dim3 grid(ceil_div(HD, BN), ceil_div(Nn, BM));
        gemm_tn_kernel<<<grid, 256>>>(h, IN_F, Wg1, IN_F, feat1, HD, nullptr, Nn, HD, IN_F);
        gemm_tn_kernel<<<grid, 256>>>(h, IN_F, Wg2, IN_F, feat2, HD, nullptr, Nn, HD, IN_F);
    }
    // el / er
    {
        int grid = ceil_div(Nn * HH * 32, 256);
        elr_kernel<<<grid, 256>>>(feat1, al1, ar1, el1, er1, Nn);
        elr_kernel<<<grid, 256>>>(feat2, al2, ar2, el2, er2, Nn);
    }
    // fused softmax + aggregate (writes sem with bias folded in)
    {
        int grid = ceil_div(Nn * 32, 256);
        gat_aggregate_kernel<<<grid, 256>>>(off1, csr1, el1, er1, feat1, b1, 0,  Nn);
        gat_aggregate_kernel<<<grid, 256>>>(off2, csr2, el2, er2, feat2, b2, HD, Nn);
    }
    // FC
    {
        dim3 grid(ceil_div(HD, BN), ceil_div(Nn, BM));
        gemm_tn_kernel<<<grid, 256>>>(sem, HD2, Wfc, HD2, out, HD, bfc, Nn, HD, HD2);
    }
}

// round 7
// speedup vs baseline: 4.0954x; 1.6598x over previous
#include <cuda_runtime.h>
#include <cuda_bf16.h>
#include <math.h>
#include <stdint.h>

#define NNODES 50000
#define EMAXE  800000
#define IN_F   256
#define HH     4
#define DD     64
#define HD     256
#define HD2    512
#define NEG_SLOPE 0.2f

// ---------------- scratch (static __device__, no allocs) ----------------
__device__ __align__(16) float g_feat1[NNODES * HD];
__device__ __align__(16) float g_feat2[NNODES * HD];
__device__ __align__(16) float g_el1[NNODES * HH], g_er1[NNODES * HH];
__device__ __align__(16) float g_el2[NNODES * HH], g_er2[NNODES * HH];

// bf16 split operands
__device__ __align__(16) __nv_bfloat16 g_h_hi[NNODES * IN_F],  g_h_lo[NNODES * IN_F];
__device__ __align__(16) __nv_bfloat16 g_semh[NNODES * HD2],   g_seml[NNODES * HD2];
__device__ __align__(16) __nv_bfloat16 g_wg1h[HD * IN_F],  g_wg1l[HD * IN_F];
__device__ __align__(16) __nv_bfloat16 g_wg2h[HD * IN_F],  g_wg2l[HD * IN_F];
__device__ __align__(16) __nv_bfloat16 g_wfch[HD * HD2],   g_wfcl[HD * HD2];

// CSR-by-dst scratch
__device__ int g_cnt1[NNODES],  g_cnt2[NNODES];
__device__ int g_off1[NNODES + 1], g_off2[NNODES + 1];
__device__ int g_cur1[NNODES],  g_cur2[NNODES];
__device__ int g_csr1[EMAXE],   g_csr2[EMAXE];
__device__ int g_part1[64],     g_part2[64];

// ================= helpers =================
__device__ __forceinline__ uint32_t smem_u32(const void* p) {
    uint32_t a;
    asm("{ .reg .u64 t; cvta.to.shared.u64 t, %1; cvt.u32.u64 %0, t; }" : "=r"(a) : "l"(p));
    return a;
}

#define LDSM_X4(r0, r1, r2, r3, addr) \
    asm volatile("ldmatrix.sync.aligned.m8n8.x4.shared.b16 {%0,%1,%2,%3}, [%4];" \
                 : "=r"(r0), "=r"(r1), "=r"(r2), "=r"(r3) : "r"(addr))

#define MMA_16816(d, a0, a1, a2, a3, b0, b1) \
    asm volatile("mma.sync.aligned.m16n8k16.row.col.f32.bf16.bf16.f32 " \
                 "{%0,%1,%2,%3}, {%4,%5,%6,%7}, {%8,%9}, {%0,%1,%2,%3};" \
                 : "+f"((d)[0]), "+f"((d)[1]), "+f"((d)[2]), "+f"((d)[3]) \
                 : "r"(a0), "r"(a1), "r"(a2), "r"(a3), "r"(b0), "r"(b1))

// ================= fp32 -> bf16 hi/lo split =================
__global__ void split_kernel(const float* __restrict__ x,
                             __nv_bfloat16* __restrict__ hi,
                             __nv_bfloat16* __restrict__ lo, int n4)
{
    int i = blockIdx.x * blockDim.x + threadIdx.x;
    if (i >= n4) return;
    float4 v = ((const float4*)x)[i];
    float vv[4] = {v.x, v.y, v.z, v.w};
    __align__(8) __nv_bfloat16 hb[4], lb[4];
#pragma unroll
    for (int k = 0; k < 4; k++) {
        hb[k] = __float2bfloat16(vv[k]);
        lb[k] = __float2bfloat16(vv[k] - __bfloat162float(hb[k]));
    }
    ((uint2*)hi)[i] = *(uint2*)hb;
    ((uint2*)lo)[i] = *(uint2*)lb;
}

// ================= split-bf16 GEMM via mma.sync (HMMA) =================
// C[m,n] = sum_k A[m,k]*B[n,k] (+ bias[n] if bias != nullptr)
// A = Ah+Al, B = Bh+Bl bf16 splits; D accumulates Ah*Bh + Ah*Bl + Al*Bh in fp32.
// Block tile 128x128, K-step 32. 256 threads = 8 warps in 2(m) x 4(n).
#define GK 32
#define GSTR 40    // padded smem row stride in bf16 (80B: conflict-free ldmatrix)

__global__ void __launch_bounds__(256, 1)
mma_gemm_kernel(const __nv_bfloat16* __restrict__ Ah, const __nv_bfloat16* __restrict__ Al,
                const __nv_bfloat16* __restrict__ Bh, const __nv_bfloat16* __restrict__ Bl,
                int M, int K,
                float* __restrict__ C,                 // ld = 256
                const float* __restrict__ bias)
{
    __shared__ __align__(16) __nv_bfloat16 sAh[128 * GSTR];
    __shared__ __align__(16) __nv_bfloat16 sAl[128 * GSTR];
    __shared__ __align__(16) __nv_bfloat16 sBh[128 * GSTR];
    __shared__ __align__(16) __nv_bfloat16 sBl[128 * GSTR];

    const int tid = threadIdx.x;
    const int lane = tid & 31;
    const int wid = tid >> 5;
    const int wm = wid >> 2;          // 0..1
    const int wn = wid & 3;           // 0..3
    const int m0 = blockIdx.y * 128, n0 = blockIdx.x * 128;

    const uint32_t sbAh = smem_u32(sAh), sbAl = smem_u32(sAl);
    const uint32_t sbBh = smem_u32(sBh), sbBl = smem_u32(sBl);

    float acc[4][4][4];
#pragma unroll
    for (int i = 0; i < 4; i++)
#pragma unroll
        for (int j = 0; j < 4; j++)
#pragma unroll
            for (int r = 0; r < 4; r++) acc[i][j][r] = 0.f;

    // ldmatrix source addresses (fixed per thread, offset by k-step)
    const int a_row = (lane & 15);
    const int a_kof = (lane >> 4) << 3;
    const int b_row = (lane & 7) + ((lane >> 4) << 3);
    const int b_kof = ((lane >> 3) & 1) << 3;

    for (int kc = 0; kc < K; kc += GK) {
        // ---- load 128x32 tiles of Ah/Al/Bh/Bl ----
#pragma unroll
        for (int u = 0; u < 2; u++) {
            int c = tid * 2 + u;                 // 0..511 16B-chunks
            int row = c >> 2, cc = c & 3;
            size_t goff = (size_t)row * K + kc + cc * 8;
            uint32_t soff = (uint32_t)(row * GSTR + cc * 8) * 2;
            int m = m0 + row;
            uint4 vh = make_uint4(0, 0, 0, 0), vl = make_uint4(0, 0, 0, 0);
            if (m < M) {
                vh = *(const uint4*)(Ah + (size_t)m * K + kc + cc * 8);
                vl = *(const uint4*)(Al + (size_t)m * K + kc + cc * 8);
            }
            *(uint4*)((char*)sAh + soff) = vh;
            *(uint4*)((char*)sAl + soff) = vl;
            int n = n0 + row;                    // weight rows: always < 256
            *(uint4*)((char*)sBh + soff) = *(const uint4*)(Bh + (size_t)n * K + goff - (size_t)row * K - kc + kc);
            *(uint4*)((char*)sBl + soff) = *(const uint4*)(Bl + (size_t)n * K + kc + cc * 8);
        }
        __syncthreads();

#pragma unroll
        for (int k0 = 0; k0 < GK; k0 += 16) {
            uint32_t bh[4][2], bl[4][2];
#pragma unroll
            for (int g = 0; g < 2; g++) {
                int nrow = wn * 32 + g * 16 + b_row;
                uint32_t ba = (uint32_t)(nrow * GSTR + k0 + b_kof) * 2;
                uint32_t r0, r1, r2, r3;
                LDSM_X4(r0, r1, r2, r3, sbBh + ba);
                bh[g * 2][0] = r0; bh[g * 2][1] = r1;
                bh[g * 2 + 1][0] = r2; bh[g * 2 + 1][1] = r3;
                LDSM_X4(r0, r1, r2, r3, sbBl + ba);
                bl[g * 2][0] = r0; bl[g * 2][1] = r1;
                bl[g * 2 + 1][0] = r2; bl[g * 2 + 1][1] = r3;
            }
#pragma unroll
            for (int im = 0; im < 4; im++) {
                int arow = wm * 64 + im * 16 + a_row;
                uint32_t aa = (uint32_t)(arow * GSTR + k0 + a_kof) * 2;
                uint32_t ah0, ah1, ah2, ah3, al0, al1, al2, al3;
                LDSM_X4(ah0, ah1, ah2, ah3, sbAh + aa);
                LDSM_X4(al0, al1, al2, al3, sbAl + aa);
#pragma unroll
                for (int in = 0; in < 4; in++) {
                    MMA_16816(acc[im][in], ah0, ah1, ah2, ah3, bh[in][0], bh[in][1]);
                    MMA_16816(acc[im][in], ah0, ah1, ah2, ah3, bl[in][0], bl[in][1]);
                    MMA_16816(acc[im][in], al0, al1, al2, al3, bh[in][0], bh[in][1]);
                }
            }
        }
        __syncthreads();
    }

    // ---- epilogue ----
#pragma unroll
    for (int im = 0; im < 4; im++) {
#pragma unroll
        for (int in = 0; in < 4; in++) {
            int row0 = m0 + wm * 64 + im * 16 + (lane >> 2);
            int col  = n0 + wn * 32 + in * 8 + (lane & 3) * 2;
            float bx = 0.f, by = 0.f;
            if (bias) { bx = bias[col]; by = bias[col + 1]; }
            if (row0 < M)
                *(float2*)(C + (size_t)row0 * HD + col) =
                    make_float2(acc[im][in][0] + bx, acc[im][in][1] + by);
            int row1 = row0 + 8;
            if (row1 < M)
                *(float2*)(C + (size_t)row1 * HD + col) =
                    make_float2(acc[im][in][2] + bx, acc[im][in][3] + by);
        }
    }
}

// ================= el/er: warp per (node, head) dot over D=64 =================
__global__ void elr_kernel(const float* __restrict__ feat,
                           const float* __restrict__ al, const float* __restrict__ ar,
                           float* __restrict__ el, float* __restrict__ er, int Nn)
{
    int w = (blockIdx.x * blockDim.x + threadIdx.x) >> 5;
    int lane = threadIdx.x & 31;
    if (w >= Nn * HH) return;
    int n = w / HH, hh = w % HH;
    const float2* f = (const float2*)(feat + (size_t)n * HD + hh * DD);
    const float2* a = (const float2*)(al + hh * DD);
    const float2* r = (const float2*)(ar + hh * DD);
    float2 fv = f[lane], av = a[lane], rv = r[lane];
    float sl = fv.x * av.x + fv.y * av.y;
    float sr = fv.x * rv.x + fv.y * rv.y;
#pragma unroll
    for (int o = 16; o; o >>= 1) {
        sl += __shfl_xor_sync(0xffffffffu, sl, o);
        sr += __shfl_xor_sync(0xffffffffu, sr, o);
    }
    if (lane == 0) { el[n * HH + hh] = sl; er[n * HH + hh] = sr; }
}

// ================= CSR build =================
__global__ void zero_cnt_kernel(int Nn)
{
    int i = blockIdx.x * blockDim.x + threadIdx.x;
    if (i < Nn) { g_cnt1[i] = 0; g_cnt2[i] = 0; }
}

__global__ void hist_kernel(const int* __restrict__ dst, int* __restrict__ cnt, int E)
{
    int e = blockIdx.x * blockDim.x + threadIdx.x;
    if (e < E) atomicAdd(&cnt[dst[e]], 1);
}

__global__ void partial_kernel(const int* __restrict__ cnt, int* __restrict__ part, int Nn)
{
    __shared__ int sred[256];
    int tid = threadIdx.x;
    int base = blockIdx.x * 1024;
    int sum = 0;
#pragma unroll
    for (int j = 0; j < 4; j++) {
        int i = base + j * 256 + tid;
        if (i < Nn) sum += cnt[i];
    }
    sred[tid] = sum;
    __syncthreads();
#pragma unroll
    for (int o = 128; o; o >>= 1) {
        if (tid < o) sred[tid] += sred[tid + o];
        __syncthreads();
    }
    if (tid == 0) part[blockIdx.x] = sred[0];
}

__global__ void top_scan_kernel(int* __restrict__ part, int nb)
{
    if (threadIdx.x == 0 && blockIdx.x == 0) {
        int run = 0;
        for (int i = 0; i < nb; i++) { int v = part[i]; part[i] = run; run += v; }
    }
}

__global__ void final_scan_kernel(const int* __restrict__ cnt, const int* __restrict__ part,
                                  int* __restrict__ off, int* __restrict__ cur, int Nn, int E)
{
    __shared__ int s[256];
    int tid = threadIdx.x;
    int base = blockIdx.x * 1024;
    int v[4]; int loc = 0;
#pragma unroll
    for (int j = 0; j < 4; j++) {
        int i = base + tid * 4 + j;
        v[j] = (i < Nn) ? cnt[i] : 0;
        loc += v[j];
    }
    s[tid] = loc;
    __syncthreads();
#pragma unroll
    for (int o = 1; o < 256; o <<= 1) {
        int t = (tid >= o) ? s[tid - o] : 0;
        __syncthreads();
        s[tid] += t;
        __syncthreads();
    }
    int run = part[blockIdx.x] + s[tid] - loc;
#pragma unroll
    for (int j = 0; j < 4; j++) {
        int i = base + tid * 4 + j;
        if (i < Nn) { off[i] = run; cur[i] = run; run += v[j]; }
    }
    if (blockIdx.x == 0 && tid == 0) off[Nn] = E;
}

__global__ void fill_kernel(const int* __restrict__ src, const int* __restrict__ dst,
                            int* __restrict__ cursor, int* __restrict__ csr, int E)
{
    int e = blockIdx.x * blockDim.x + threadIdx.x;
    if (e >= E) return;
    int pos = atomicAdd(&cursor[dst[e]], 1);
    csr[pos] = src[e];
}

// ================= fused GAT aggregate: warp per dst node =================
// Writes sem columns [rel_off, rel_off+256) as bf16 hi/lo (bias folded).
__global__ void gat_aggregate_kernel(const int* __restrict__ off, const int* __restrict__ csr,
                                     const float* __restrict__ el, const float* __restrict__ er,
                                     const float* __restrict__ feat,
                                     const float* __restrict__ bias,
                                     int rel_off, int Nn)
{
    int n = (blockIdx.x * blockDim.x + threadIdx.x) >> 5;
    int lane = threadIdx.x & 31;
    if (n >= Nn) return;

    const int beg = off[n], end = off[n + 1];
    float4 er4 = *(const float4*)(er + n * HH);

    float4 m = make_float4(-INFINITY, -INFINITY, -INFINITY, -INFINITY);
    for (int k = beg + lane; k < end; k += 32) {
        int s = csr[k];
        float4 l = *(const float4*)(el + s * HH);
        float4 e;
        e.x = l.x + er4.x; e.x = e.x > 0.f ? e.x : NEG_SLOPE * e.x;
        e.y = l.y + er4.y; e.y = e.y > 0.f ? e.y : NEG_SLOPE * e.y;
        e.z = l.z + er4.z; e.z = e.z > 0.f ? e.z : NEG_SLOPE * e.z;
        e.w = l.w + er4.w; e.w = e.w > 0.f ? e.w : NEG_SLOPE * e.w;
        m.x = fmaxf(m.x, e.x); m.y = fmaxf(m.y, e.y);
        m.z = fmaxf(m.z, e.z); m.w = fmaxf(m.w, e.w);
    }
#pragma unroll
    for (int o = 16; o; o >>= 1) {
        m.x = fmaxf(m.x, __shfl_xor_sync(0xffffffffu, m.x, o));
        m.y = fmaxf(m.y, __shfl_xor_sync(0xffffffffu, m.y, o));
        m.z = fmaxf(m.z, __shfl_xor_sync(0xffffffffu, m.z, o));
        m.w = fmaxf(m.w, __shfl_xor_sync(0xffffffffu, m.w, o));
    }

    float4 ds = make_float4(0.f, 0.f, 0.f, 0.f);
    for (int k = beg + lane; k < end; k += 32) {
        int s = csr[k];
        float4 l = *(const float4*)(el + s * HH);
        float4 e;
        e.x = l.x + er4.x; e.x = e.x > 0.f ? e.x : NEG_SLOPE * e.x;
        e.y = l.y + er4.y; e.y = e.y > 0.f ? e.y : NEG_SLOPE * e.y;
        e.z = l.z + er4.z; e.z = e.z > 0.f ? e.z : NEG_SLOPE * e.z;
        e.w = l.w + er4.w; e.w = e.w > 0.f ? e.w : NEG_SLOPE * e.w;
        ds.x += __expf(e.x - m.x); ds.y += __expf(e.y - m.y);
        ds.z += __expf(e.z - m.z); ds.w += __expf(e.w - m.w);
    }
#pragma unroll
    for (int o = 16; o; o >>= 1) {
        ds.x += __shfl_xor_sync(0xffffffffu, ds.x, o);
        ds.y += __shfl_xor_sync(0xffffffffu, ds.y, o);
        ds.z += __shfl_xor_sync(0xffffffffu, ds.z, o);
        ds.w += __shfl_xor_sync(0xffffffffu, ds.w, o);
    }

    const int head = lane >> 3;
    const float mh   = head == 0 ? m.x  : head == 1 ? m.y  : head == 2 ? m.z  : m.w;
    const float dh   = head == 0 ? ds.x : head == 1 ? ds.y : head == 2 ? ds.z : ds.w;
    const float erh  = head == 0 ? er4.x: head == 1 ? er4.y: head == 2 ? er4.z: er4.w;
    const float invd = 1.0f / dh;

    float acc[8];
#pragma unroll
    for (int i = 0; i < 8; i++) acc[i] = 0.f;

    for (int base = beg; base < end; base += 32) {
        int myidx = (base + lane < end) ? csr[base + lane] : 0;
        int cnt = min(32, end - base);
#pragma unroll 2
        for (int j = 0; j < cnt; j++) {
            int s = __shfl_sync(0xffffffffu, myidx, j);
            float e = el[s * HH + head] + erh;
            e = e > 0.f ? e : NEG_SLOPE * e;
            float alpha = __expf(e - mh) * invd;
            const float4* fp = (const float4*)(feat + (size_t)s * HD + lane * 8);
            float4 a = fp[0], b = fp[1];
            acc[0] = fmaf(a.x, alpha, acc[0]);
            acc[1] = fmaf(a.y, alpha, acc[1]);
            acc[2] = fmaf(a.z, alpha, acc[2]);
            acc[3] = fmaf(a.w, alpha, acc[3]);
            acc[4] = fmaf(b.x, alpha, acc[4]);
            acc[5] = fmaf(b.y, alpha, acc[5]);
            acc[6] = fmaf(b.z, alpha, acc[6]);
            acc[7] = fmaf(b.w, alpha, acc[7]);
        }
    }

    float4 bo0 = *(const float4*)(bias + lane * 8);
    float4 bo1 = *(const float4*)(bias + lane * 8 + 4);
    float w[8];
    w[0] = acc[0] + bo0.x; w[1] = acc[1] + bo0.y; w[2] = acc[2] + bo0.z; w[3] = acc[3] + bo0.w;
    w[4] = acc[4] + bo1.x; w[5] = acc[5] + bo1.y; w[6] = acc[6] + bo1.z; w[7] = acc[7] + bo1.w;

    __align__(16) __nv_bfloat16 hb[8], lb[8];
#pragma unroll
    for (int i = 0; i < 8; i++) {
        hb[i] = __float2bfloat16(w[i]);
        lb[i] = __float2bfloat16(w[i] - __bfloat162float(hb[i]));
    }
    size_t didx = (size_t)n * HD2 + rel_off + lane * 8;
    *(uint4*)(g_semh + didx) = *(uint4*)hb;
    *(uint4*)(g_seml + didx) = *(uint4*)lb;
}

// ================= launch =================
static inline int ceil_div(int a, int b) { return (a + b - 1) / b; }

extern "C" void kernel_launch(void* const* d_in, const int* in_sizes, int n_in,
                              void* d_out, int out_size)
{
    const float* h    = (const float*)d_in[0];
    const float* Wg1  = (const float*)d_in[1];
    const float* al1  = (const float*)d_in[2];
    const float* ar1  = (const float*)d_in[3];
    const float* b1   = (const float*)d_in[4];
    const float* Wg2  = (const float*)d_in[5];
    const float* al2  = (const float*)d_in[6];
    const float* ar2  = (const float*)d_in[7];
    const float* b2   = (const float*)d_in[8];
    const float* Wfc  = (const float*)d_in[9];
    const float* bfc  = (const float*)d_in[10];
    const int*   src1 = (const int*)d_in[11];
    const int*   dst1 = (const int*)d_in[12];
    const int*   src2 = (const int*)d_in[13];
    const int*   dst2 = (const int*)d_in[14];
    float* out = (float*)d_out;

    const int Nn = in_sizes[0] / IN_F;
    const int E1 = in_sizes[11];
    const int E2 = in_sizes[13];

    float *feat1, *feat2, *el1, *er1, *el2, *er2;
    __nv_bfloat16 *hhi, *hlo, *semh, *seml;
    __nv_bfloat16 *wg1h, *wg1l, *wg2h, *wg2l, *wfch, *wfcl;
    int *cnt1, *cnt2, *off1, *off2, *cur1, *cur2, *csr1, *csr2, *part1, *part2;
    cudaGetSymbolAddress((void**)&feat1, g_feat1);
    cudaGetSymbolAddress((void**)&feat2, g_feat2);
    cudaGetSymbolAddress((void**)&el1,   g_el1);
    cudaGetSymbolAddress((void**)&er1,   g_er1);
    cudaGetSymbolAddress((void**)&el2,   g_el2);
    cudaGetSymbolAddress((void**)&er2,   g_er2);
    cudaGetSymbolAddress((void**)&hhi,   g_h_hi);
    cudaGetSymbolAddress((void**)&hlo,   g_h_lo);
    cudaGetSymbolAddress((void**)&semh,  g_semh);
    cudaGetSymbolAddress((void**)&seml,  g_seml);
    cudaGetSymbolAddress((void**)&wg1h,  g_wg1h);
    cudaGetSymbolAddress((void**)&wg1l,  g_wg1l);
    cudaGetSymbolAddress((void**)&wg2h,  g_wg2h);
    cudaGetSymbolAddress((void**)&wg2l,  g_wg2l);
    cudaGetSymbolAddress((void**)&wfch,  g_wfch);
    cudaGetSymbolAddress((void**)&wfcl,  g_wfcl);
    cudaGetSymbolAddress((void**)&cnt1,  g_cnt1);
    cudaGetSymbolAddress((void**)&cnt2,  g_cnt2);
    cudaGetSymbolAddress((void**)&off1,  g_off1);
    cudaGetSymbolAddress((void**)&off2,  g_off2);
    cudaGetSymbolAddress((void**)&cur1,  g_cur1);
    cudaGetSymbolAddress((void**)&cur2,  g_cur2);
    cudaGetSymbolAddress((void**)&csr1,  g_csr1);
    cudaGetSymbolAddress((void**)&csr2,  g_csr2);
    cudaGetSymbolAddress((void**)&part1, g_part1);
    cudaGetSymbolAddress((void**)&part2, g_part2);

    // --- bf16 splits of activations + weights ---
    split_kernel<<<ceil_div(Nn * IN_F / 4, 256), 256>>>(h,   hhi,  hlo,  Nn * IN_F / 4);
    split_kernel<<<ceil_div(HD * IN_F / 4, 256), 256>>>(Wg1, wg1h, wg1l, HD * IN_F / 4);
    split_kernel<<<ceil_div(HD * IN_F / 4, 256), 256>>>(Wg2, wg2h, wg2l, HD * IN_F / 4);
    split_kernel<<<ceil_div(HD * HD2 / 4, 256), 256>>>(Wfc, wfch, wfcl, HD * HD2 / 4);

    // --- CSR build ---
    const int nb = ceil_div(Nn, 1024);
    zero_cnt_kernel<<<ceil_div(Nn, 256), 256>>>(Nn);
    hist_kernel<<<ceil_div(E1, 256), 256>>>(dst1, cnt1, E1);
    hist_kernel<<<ceil_div(E2, 256), 256>>>(dst2, cnt2, E2);
    partial_kernel<<<nb, 256>>>(cnt1, part1, Nn);
    partial_kernel<<<nb, 256>>>(cnt2, part2, Nn);
    top_scan_kernel<<<1, 32>>>(part1, nb);
    top_scan_kernel<<<1, 32>>>(part2, nb);
    final_scan_kernel<<<nb, 256>>>(cnt1, part1, off1, cur1, Nn, E1);
    final_scan_kernel<<<nb, 256>>>(cnt2, part2, off2, cur2, Nn, E2);
    fill_kernel<<<ceil_div(E1, 256), 256>>>(src1, dst1, cur1, csr1, E1);
    fill_kernel<<<ceil_div(E2, 256), 256>>>(src2, dst2, cur2, csr2, E2);

    // --- projection GEMMs (HMMA, split-bf16) ---
    {
        dim3 grid(2, ceil_div(Nn, 128));
        mma_gemm_kernel<<<grid, 256>>>(hhi, hlo, wg1h, wg1l, Nn, IN_F, feat1, nullptr);
        mma_gemm_kernel<<<grid, 256>>>(hhi, hlo, wg2h, wg2l, Nn, IN_F, feat2, nullptr);
    }
    // --- el / er ---
    {
        int grid = ceil_div(Nn * HH * 32, 256);
        elr_kernel<<<grid, 256>>>(feat1, al1, ar1, el1, er1, Nn);
        elr_kernel<<<grid, 256>>>(feat2, al2, ar2, el2, er2, Nn);
    }
    // --- fused softmax + aggregate (writes sem hi/lo with bias folded) ---
    {
        int grid = ceil_div(Nn * 32, 256);
        gat_aggregate_kernel<<<grid, 256>>>(off1, csr1, el1, er1, feat1, b1, 0,  Nn);
        gat_aggregate_kernel<<<grid, 256>>>(off2, csr2, el2, er2, feat2, b2, HD, Nn);
    }
    // --- FC GEMM (HMMA, split-bf16) ---
    {
        dim3 grid(2, ceil_div(Nn, 128));
        mma_gemm_kernel<<<grid, 256>>>(semh, seml, wfch, wfcl, Nn, HD2, out, bfc);
    }
}

// round 8
// speedup vs baseline: 5.7032x; 1.3926x over previous
#include <cuda_runtime.h>
#include <cuda_bf16.h>
#include <math.h>
#include <stdint.h>

#define NNODES 50000
#define EMAXE  800000
#define IN_F   256
#define HH     4
#define DD     64
#define HD     256
#define HD2    512
#define NEG_SLOPE 0.2f

// ---------------- scratch (static __device__, no allocs) ----------------
__device__ __align__(16) float g_feat1[NNODES * HD];
__device__ __align__(16) float g_feat2[NNODES * HD];
__device__ __align__(16) float g_el1[NNODES * HH], g_er1[NNODES * HH];
__device__ __align__(16) float g_el2[NNODES * HH], g_er2[NNODES * HH];

// bf16 split operands
__device__ __align__(16) __nv_bfloat16 g_h_hi[NNODES * IN_F],  g_h_lo[NNODES * IN_F];
__device__ __align__(16) __nv_bfloat16 g_semh[NNODES * HD2],   g_seml[NNODES * HD2];
__device__ __align__(16) __nv_bfloat16 g_wgh[HD2 * IN_F], g_wgl[HD2 * IN_F];   // Wg1 rows 0-255, Wg2 rows 256-511
__device__ __align__(16) __nv_bfloat16 g_wfch[HD * HD2],  g_wfcl[HD * HD2];

// CSR-by-dst scratch
__device__ int g_cnt1[NNODES],  g_cnt2[NNODES];
__device__ int g_off1[NNODES + 1], g_off2[NNODES + 1];
__device__ int g_cur1[NNODES],  g_cur2[NNODES];
__device__ int g_csr1[EMAXE],   g_csr2[EMAXE];
__device__ int g_part1[64],     g_part2[64];

// ================= helpers =================
__device__ __forceinline__ uint32_t smem_u32(const void* p) {
    uint32_t a;
    asm("{ .reg .u64 t; cvta.to.shared.u64 t, %1; cvt.u32.u64 %0, t; }" : "=r"(a) : "l"(p));
    return a;
}

#define LDSM_X4(r0, r1, r2, r3, addr) \
    asm volatile("ldmatrix.sync.aligned.m8n8.x4.shared.b16 {%0,%1,%2,%3}, [%4];" \
                 : "=r"(r0), "=r"(r1), "=r"(r2), "=r"(r3) : "r"(addr))

#define MMA_16816(d, a0, a1, a2, a3, b0, b1) \
    asm volatile("mma.sync.aligned.m16n8k16.row.col.f32.bf16.bf16.f32 " \
                 "{%0,%1,%2,%3}, {%4,%5,%6,%7}, {%8,%9}, {%0,%1,%2,%3};" \
                 : "+f"((d)[0]), "+f"((d)[1]), "+f"((d)[2]), "+f"((d)[3]) \
                 : "r"(a0), "r"(a1), "r"(a2), "r"(a3), "r"(b0), "r"(b1))

#define CP16(dst, src) \
    asm volatile("cp.async.cg.shared.global [%0], [%1], 16;" :: "r"(dst), "l"(src))
#define CP_COMMIT() asm volatile("cp.async.commit_group;" ::: "memory")
#define CP_WAIT1()  asm volatile("cp.async.wait_group 1;" ::: "memory")

// ================= fp32 -> bf16 hi/lo split =================
__global__ void split_kernel(const float* __restrict__ x,
                             __nv_bfloat16* __restrict__ hi,
                             __nv_bfloat16* __restrict__ lo, int n4)
{
    int i = blockIdx.x * blockDim.x + threadIdx.x;
    if (i >= n4) return;
    float4 v = ((const float4*)x)[i];
    float vv[4] = {v.x, v.y, v.z, v.w};
    __align__(8) __nv_bfloat16 hb[4], lb[4];
#pragma unroll
    for (int k = 0; k < 4; k++) {
        hb[k] = __float2bfloat16(vv[k]);
        lb[k] = __float2bfloat16(vv[k] - __bfloat162float(hb[k]));
    }
    ((uint2*)hi)[i] = *(uint2*)hb;
    ((uint2*)lo)[i] = *(uint2*)lb;
}

// ================= split-bf16 GEMM via mma.sync, cp.async 2-stage =================
// C[m,n] = sum_k A[m,k]*B[n,k].  3-term split: Ah*Bh + Ah*Bl + Al*Bh, fp32 accum.
// Block tile 128x128, K-step 32, 256 threads (8 warps, 2m x 4n).
// mode 0: projection — B is combined 512-row weight; writes feat1/feat2 and fused el/er.
// mode 1: FC — writes C (+bias).
#define GK 32
#define GSTR 40
#define TB 10240                     // one 128x32 bf16 tile, padded
#define STG (4 * TB)                 // Ah|Al|Bh|Bl per stage
#define GSM_TOTAL (2 * STG)          // 81920 B

__device__ __forceinline__ void load_chunk(uint32_t sbs,
    const __nv_bfloat16* __restrict__ Ah, const __nv_bfloat16* __restrict__ Al,
    const __nv_bfloat16* __restrict__ Bh, const __nv_bfloat16* __restrict__ Bl,
    int m0, int n0, int M, int K, int kc, int tid)
{
#pragma unroll
    for (int u = 0; u < 2; u++) {
        int c = tid * 2 + u;
        int row = c >> 2, cc = c & 3;
        uint32_t soff = (uint32_t)(row * GSTR + cc * 8) * 2;
        int m = m0 + row;
        if (m < M) {
            size_t ga = (size_t)m * K + kc + cc * 8;
            CP16(sbs + soff,      (const char*)(Ah + ga));
            CP16(sbs + TB + soff, (const char*)(Al + ga));
        }
        size_t gb = (size_t)(n0 + row) * K + kc + cc * 8;
        CP16(sbs + 2 * TB + soff, (const char*)(Bh + gb));
        CP16(sbs + 3 * TB + soff, (const char*)(Bl + gb));
    }
}

__global__ void __launch_bounds__(256)
mma_gemm_kernel(const __nv_bfloat16* __restrict__ Ah, const __nv_bfloat16* __restrict__ Al,
                const __nv_bfloat16* __restrict__ Bh, const __nv_bfloat16* __restrict__ Bl,
                int M, int K, int mode,
                float* __restrict__ C,                      // mode 1 output, ld 256
                float* __restrict__ feat1, float* __restrict__ feat2,
                const float* __restrict__ al1v, const float* __restrict__ ar1v,
                const float* __restrict__ al2v, const float* __restrict__ ar2v,
                float* __restrict__ el1, float* __restrict__ er1,
                float* __restrict__ el2, float* __restrict__ er2,
                const float* __restrict__ bias)
{
    extern __shared__ __align__(16) char dsm[];
    __shared__ float sAlv[128], sArv[128];
    __shared__ float sEl[256], sEr[256];

    const uint32_t sb = smem_u32(dsm);
    const int tid = threadIdx.x;
    const int lane = tid & 31;
    const int wid = tid >> 5;
    const int wm = wid >> 2;          // 0..1
    const int wn = wid & 3;           // 0..3
    const int m0 = blockIdx.y * 128, n0 = blockIdx.x * 128;

    const int rel = (n0 >= HD) ? 1 : 0;       // mode 0 only
    const int ncol0 = n0 & (HD - 1);          // 0 or 128
    const int h0 = ncol0 >> 6;                // 0 or 2

    if (mode == 0 && tid < 128) {
        const float* alsel = rel ? al2v : al1v;
        const float* arsel = rel ? ar2v : ar1v;
        sAlv[tid] = alsel[h0 * 64 + tid];
        sArv[tid] = arsel[h0 * 64 + tid];
    }
    sEl[tid] = 0.f; sEr[tid] = 0.f;

    float acc[4][4][4];
#pragma unroll
    for (int i = 0; i < 4; i++)
#pragma unroll
        for (int j = 0; j < 4; j++)
#pragma unroll
            for (int r = 0; r < 4; r++) acc[i][j][r] = 0.f;

    const int a_row = (lane & 15);
    const int a_kof = (lane >> 4) << 3;
    const int b_row = (lane & 7) + ((lane >> 4) << 3);
    const int b_kof = ((lane >> 3) & 1) << 3;

    const int nchunk = K / GK;
    load_chunk(sb, Ah, Al, Bh, Bl, m0, n0, M, K, 0, tid);
    CP_COMMIT();

    for (int c = 0; c < nchunk; c++) {
        if (c + 1 < nchunk)
            load_chunk(sb + ((c + 1) & 1) * STG, Ah, Al, Bh, Bl, m0, n0, M, K, (c + 1) * GK, tid);
        CP_COMMIT();
        CP_WAIT1();
        __syncthreads();

        const uint32_t sbs = sb + (c & 1) * STG;
        const uint32_t sbAh = sbs, sbAl = sbs + TB, sbBh = sbs + 2 * TB, sbBl = sbs + 3 * TB;
#pragma unroll
        for (int k0 = 0; k0 < GK; k0 += 16) {
            uint32_t bh[4][2], bl[4][2];
#pragma unroll
            for (int g = 0; g < 2; g++) {
                int nrow = wn * 32 + g * 16 + b_row;
                uint32_t ba = (uint32_t)(nrow * GSTR + k0 + b_kof) * 2;
                uint32_t r0, r1, r2, r3;
                LDSM_X4(r0, r1, r2, r3, sbBh + ba);
                bh[g * 2][0] = r0; bh[g * 2][1] = r1;
                bh[g * 2 + 1][0] = r2; bh[g * 2 + 1][1] = r3;
                LDSM_X4(r0, r1, r2, r3, sbBl + ba);
                bl[g * 2][0] = r0; bl[g * 2][1] = r1;
                bl[g * 2 + 1][0] = r2; bl[g * 2 + 1][1] = r3;
            }
#pragma unroll
            for (int im = 0; im < 4; im++) {
                int arow = wm * 64 + im * 16 + a_row;
                uint32_t aa = (uint32_t)(arow * GSTR + k0 + a_kof) * 2;
                uint32_t ah0, ah1, ah2, ah3, al0, al1, al2, al3;
                LDSM_X4(ah0, ah1, ah2, ah3, sbAh + aa);
                LDSM_X4(al0, al1, al2, al3, sbAl + aa);
#pragma unroll
                for (int in = 0; in < 4; in++) {
                    MMA_16816(acc[im][in], ah0, ah1, ah2, ah3, bh[in][0], bh[in][1]);
                    MMA_16816(acc[im][in], ah0, ah1, ah2, ah3, bl[in][0], bl[in][1]);
                    MMA_16816(acc[im][in], al0, al1, al2, al3, bh[in][0], bh[in][1]);
                }
            }
        }
        __syncthreads();
    }

    // ---- epilogue ----
    if (mode == 0) {
        float* Cf = rel ? feat2 : feat1;
        const int hl = wn >> 1;
#pragma unroll
        for (int im = 0; im < 4; im++) {
            int r0l = wm * 64 + im * 16 + (lane >> 2);
            float e0 = 0.f, e1 = 0.f, q0 = 0.f, q1 = 0.f;
#pragma unroll
            for (int in = 0; in < 4; in++) {
                int ct = wn * 32 + in * 8 + (lane & 3) * 2;
                float a0 = sAlv[ct], a1 = sAlv[ct + 1];
                float p0 = sArv[ct], p1 = sArv[ct + 1];
                e0 += acc[im][in][0] * a0 + acc[im][in][1] * a1;
                q0 += acc[im][in][0] * p0 + acc[im][in][1] * p1;
                e1 += acc[im][in][2] * a0 + acc[im][in][3] * a1;
                q1 += acc[im][in][2] * p0 + acc[im][in][3] * p1;

                int row0 = m0 + r0l;
                int col  = ncol0 + ct;
                if (row0 < M)
                    *(float2*)(Cf + (size_t)row0 * HD + col) =
                        make_float2(acc[im][in][0], acc[im][in][1]);
                if (row0 + 8 < M)
                    *(float2*)(Cf + (size_t)(row0 + 8) * HD + col) =
                        make_float2(acc[im][in][2], acc[im][in][3]);
            }
            atomicAdd(&sEl[r0l * 2 + hl], e0);
            atomicAdd(&sEr[r0l * 2 + hl], q0);
            atomicAdd(&sEl[(r0l + 8) * 2 + hl], e1);
            atomicAdd(&sEr[(r0l + 8) * 2 + hl], q1);
        }
        __syncthreads();
        if (tid < 128) {
            int m = m0 + tid;
            if (m < M) {
                float* elo = rel ? el2 : el1;
                float* ero = rel ? er2 : er1;
                elo[(size_t)m * HH + h0 + 0] = sEl[tid * 2 + 0];
                elo[(size_t)m * HH + h0 + 1] = sEl[tid * 2 + 1];
                ero[(size_t)m * HH + h0 + 0] = sEr[tid * 2 + 0];
                ero[(size_t)m * HH + h0 + 1] = sEr[tid * 2 + 1];
            }
        }
    } else {
#pragma unroll
        for (int im = 0; im < 4; im++) {
#pragma unroll
            for (int in = 0; in < 4; in++) {
                int row0 = m0 + wm * 64 + im * 16 + (lane >> 2);
                int col  = n0 + wn * 32 + in * 8 + (lane & 3) * 2;
                float bx = bias[col], by = bias[col + 1];
                if (row0 < M)
                    *(float2*)(C + (size_t)row0 * HD + col) =
                        make_float2(acc[im][in][0] + bx, acc[im][in][1] + by);
                if (row0 + 8 < M)
                    *(float2*)(C + (size_t)(row0 + 8) * HD + col) =
                        make_float2(acc[im][in][2] + bx, acc[im][in][3] + by);
            }
        }
    }
}

// ================= CSR build =================
__global__ void zero_cnt_kernel(int Nn)
{
    int i = blockIdx.x * blockDim.x + threadIdx.x;
    if (i < Nn) { g_cnt1[i] = 0; g_cnt2[i] = 0; }
}

__global__ void hist_kernel(const int* __restrict__ dst, int* __restrict__ cnt, int E)
{
    int e = blockIdx.x * blockDim.x + threadIdx.x;
    if (e < E) atomicAdd(&cnt[dst[e]], 1);
}

__global__ void partial_kernel(const int* __restrict__ cnt, int* __restrict__ part, int Nn)
{
    __shared__ int sred[256];
    int tid = threadIdx.x;
    int base = blockIdx.x * 1024;
    int sum = 0;
#pragma unroll
    for (int j = 0; j < 4; j++) {
        int i = base + j * 256 + tid;
        if (i < Nn) sum += cnt[i];
    }
    sred[tid] = sum;
    __syncthreads();
#pragma unroll
    for (int o = 128; o; o >>= 1) {
        if (tid < o) sred[tid] += sred[tid + o];
        __syncthreads();
    }
    if (tid == 0) part[blockIdx.x] = sred[0];
}

__global__ void top_scan_kernel(int* __restrict__ part, int nb)
{
    if (threadIdx.x == 0 && blockIdx.x == 0) {
        int run = 0;
        for (int i = 0; i < nb; i++) { int v = part[i]; part[i] = run; run += v; }
    }
}

__global__ void final_scan_kernel(const int* __restrict__ cnt, const int* __restrict__ part,
                                  int* __restrict__ off, int* __restrict__ cur, int Nn, int E)
{
    __shared__ int s[256];
    int tid = threadIdx.x;
    int base = blockIdx.x * 1024;
    int v[4]; int loc = 0;
#pragma unroll
    for (int j = 0; j < 4; j++) {
        int i = base + tid * 4 + j;
        v[j] = (i < Nn) ? cnt[i] : 0;
        loc += v[j];
    }
    s[tid] = loc;
    __syncthreads();
#pragma unroll
    for (int o = 1; o < 256; o <<= 1) {
        int t = (tid >= o) ? s[tid - o] : 0;
        __syncthreads();
        s[tid] += t;
        __syncthreads();
    }
    int run = part[blockIdx.x] + s[tid] - loc;
#pragma unroll
    for (int j = 0; j < 4; j++) {
        int i = base + tid * 4 + j;
        if (i < Nn) { off[i] = run; cur[i] = run; run += v[j]; }
    }
    if (blockIdx.x == 0 && tid == 0) off[Nn] = E;
}

__global__ void fill_kernel(const int* __restrict__ src, const int* __restrict__ dst,
                            int* __restrict__ cursor, int* __restrict__ csr, int E)
{
    int e = blockIdx.x * blockDim.x + threadIdx.x;
    if (e >= E) return;
    int pos = atomicAdd(&cursor[dst[e]], 1);
    csr[pos] = src[e];
}

// ================= fused GAT aggregate: warp per dst node =================
__global__ void gat_aggregate_kernel(const int* __restrict__ off, const int* __restrict__ csr,
                                     const float* __restrict__ el, const float* __restrict__ er,
                                     const float* __restrict__ feat,
                                     const float* __restrict__ bias,
                                     int rel_off, int Nn)
{
    int n = (blockIdx.x * blockDim.x + threadIdx.x) >> 5;
    int lane = threadIdx.x & 31;
    if (n >= Nn) return;

    const int beg = off[n], end = off[n + 1];
    float4 er4 = *(const float4*)(er + n * HH);

    float4 m = make_float4(-INFINITY, -INFINITY, -INFINITY, -INFINITY);
    for (int k = beg + lane; k < end; k += 32) {
        int s = csr[k];
        float4 l = *(const float4*)(el + s * HH);
        float4 e;
        e.x = l.x + er4.x; e.x = e.x > 0.f ? e.x : NEG_SLOPE * e.x;
        e.y = l.y + er4.y; e.y = e.y > 0.f ? e.y : NEG_SLOPE * e.y;
        e.z = l.z + er4.z; e.z = e.z > 0.f ? e.z : NEG_SLOPE * e.z;
        e.w = l.w + er4.w; e.w = e.w > 0.f ? e.w : NEG_SLOPE * e.w;
        m.x = fmaxf(m.x, e.x); m.y = fmaxf(m.y, e.y);
        m.z = fmaxf(m.z, e.z); m.w = fmaxf(m.w, e.w);
    }
#pragma unroll
    for (int o = 16; o; o >>= 1) {
        m.x = fmaxf(m.x, __shfl_xor_sync(0xffffffffu, m.x, o));
        m.y = fmaxf(m.y, __shfl_xor_sync(0xffffffffu, m.y, o));
        m.z = fmaxf(m.z, __shfl_xor_sync(0xffffffffu, m.z, o));
        m.w = fmaxf(m.w, __shfl_xor_sync(0xffffffffu, m.w, o));
    }

    float4 ds = make_float4(0.f, 0.f, 0.f, 0.f);
    for (int k = beg + lane; k < end; k += 32) {
        int s = csr[k];
        float4 l = *(const float4*)(el + s * HH);
        float4 e;
        e.x = l.x + er4.x; e.x = e.x > 0.f ? e.x : NEG_SLOPE * e.x;
        e.y = l.y + er4.y; e.y = e.y > 0.f ? e.y : NEG_SLOPE * e.y;
        e.z = l.z + er4.z; e.z = e.z > 0.f ? e.z : NEG_SLOPE * e.z;
        e.w = l.w + er4.w; e.w = e.w > 0.f ? e.w : NEG_SLOPE * e.w;
        ds.x += __expf(e.x - m.x); ds.y += __expf(e.y - m.y);
        ds.z += __expf(e.z - m.z); ds.w += __expf(e.w - m.w);
    }
#pragma unroll
    for (int o = 16; o; o >>= 1) {
        ds.x += __shfl_xor_sync(0xffffffffu, ds.x, o);
        ds.y += __shfl_xor_sync(0xffffffffu, ds.y, o);
        ds.z += __shfl_xor_sync(0xffffffffu, ds.z, o);
        ds.w += __shfl_xor_sync(0xffffffffu, ds.w, o);
    }

    const int head = lane >> 3;
    const float mh   = head == 0 ? m.x  : head == 1 ? m.y  : head == 2 ? m.z  : m.w;
    const float dh   = head == 0 ? ds.x : head == 1 ? ds.y : head == 2 ? ds.z : ds.w;
    const float erh  = head == 0 ? er4.x: head == 1 ? er4.y: head == 2 ? er4.z: er4.w;
    const float invd = 1.0f / dh;

    float acc[8];
#pragma unroll
    for (int i = 0; i < 8; i++) acc[i] = 0.f;

    for (int base = beg; base < end; base += 32) {
        int myidx = (base + lane < end) ? csr[base + lane] : 0;
        int cnt = min(32, end - base);
#pragma unroll 2
        for (int j = 0; j < cnt; j++) {
            int s = __shfl_sync(0xffffffffu, myidx, j);
            float e = el[s * HH + head] + erh;
            e = e > 0.f ? e : NEG_SLOPE * e;
            float alpha = __expf(e - mh) * invd;
            const float4* fp = (const float4*)(feat + (size_t)s * HD + lane * 8);
            float4 a = fp[0], b = fp[1];
            acc[0] = fmaf(a.x, alpha, acc[0]);
            acc[1] = fmaf(a.y, alpha, acc[1]);
            acc[2] = fmaf(a.z, alpha, acc[2]);
            acc[3] = fmaf(a.w, alpha, acc[3]);
            acc[4] = fmaf(b.x, alpha, acc[4]);
            acc[5] = fmaf(b.y, alpha, acc[5]);
            acc[6] = fmaf(b.z, alpha, acc[6]);
            acc[7] = fmaf(b.w, alpha, acc[7]);
        }
    }

    float4 bo0 = *(const float4*)(bias + lane * 8);
    float4 bo1 = *(const float4*)(bias + lane * 8 + 4);
    float w[8];
    w[0] = acc[0] + bo0.x; w[1] = acc[1] + bo0.y; w[2] = acc[2] + bo0.z; w[3] = acc[3] + bo0.w;
    w[4] = acc[4] + bo1.x; w[5] = acc[5] + bo1.y; w[6] = acc[6] + bo1.z; w[7] = acc[7] + bo1.w;

    __align__(16) __nv_bfloat16 hb[8], lb[8];
#pragma unroll
    for (int i = 0; i < 8; i++) {
        hb[i] = __float2bfloat16(w[i]);
        lb[i] = __float2bfloat16(w[i] - __bfloat162float(hb[i]));
    }
    size_t didx = (size_t)n * HD2 + rel_off + lane * 8;
    *(uint4*)(g_semh + didx) = *(uint4*)hb;
    *(uint4*)(g_seml + didx) = *(uint4*)lb;
}

// ================= launch =================
static inline int ceil_div(int a, int b) { return (a + b - 1) / b; }

extern "C" void kernel_launch(void* const* d_in, const int* in_sizes, int n_in,
                              void* d_out, int out_size)
{
    const float* h    = (const float*)d_in[0];
    const float* Wg1  = (const float*)d_in[1];
    const float* al1  = (const float*)d_in[2];
    const float* ar1  = (const float*)d_in[3];
    const float* b1   = (const float*)d_in[4];
    const float* Wg2  = (const float*)d_in[5];
    const float* al2  = (const float*)d_in[6];
    const float* ar2  = (const float*)d_in[7];
    const float* b2   = (const float*)d_in[8];
    const float* Wfc  = (const float*)d_in[9];
    const float* bfc  = (const float*)d_in[10];
    const int*   src1 = (const int*)d_in[11];
    const int*   dst1 = (const int*)d_in[12];
    const int*   src2 = (const int*)d_in[13];
    const int*   dst2 = (const int*)d_in[14];
    float* out = (float*)d_out;

    const int Nn = in_sizes[0] / IN_F;
    const int E1 = in_sizes[11];
    const int E2 = in_sizes[13];

    float *feat1, *feat2, *el1, *er1, *el2, *er2;
    __nv_bfloat16 *hhi, *hlo, *semh, *seml, *wgh, *wgl, *wfch, *wfcl;
    int *cnt1, *cnt2, *off1, *off2, *cur1, *cur2, *csr1, *csr2, *part1, *part2;
    cudaGetSymbolAddress((void**)&feat1, g_feat1);
    cudaGetSymbolAddress((void**)&feat2, g_feat2);
    cudaGetSymbolAddress((void**)&el1,   g_el1);
    cudaGetSymbolAddress((void**)&er1,   g_er1);
    cudaGetSymbolAddress((void**)&el2,   g_el2);
    cudaGetSymbolAddress((void**)&er2,   g_er2);
    cudaGetSymbolAddress((void**)&hhi,   g_h_hi);
    cudaGetSymbolAddress((void**)&hlo,   g_h_lo);
    cudaGetSymbolAddress((void**)&semh,  g_semh);
    cudaGetSymbolAddress((void**)&seml,  g_seml);
    cudaGetSymbolAddress((void**)&wgh,   g_wgh);
    cudaGetSymbolAddress((void**)&wgl,   g_wgl);
    cudaGetSymbolAddress((void**)&wfch,  g_wfch);
    cudaGetSymbolAddress((void**)&wfcl,  g_wfcl);
    cudaGetSymbolAddress((void**)&cnt1,  g_cnt1);
    cudaGetSymbolAddress((void**)&cnt2,  g_cnt2);
    cudaGetSymbolAddress((void**)&off1,  g_off1);
    cudaGetSymbolAddress((void**)&off2,  g_off2);
    cudaGetSymbolAddress((void**)&cur1,  g_cur1);
    cudaGetSymbolAddress((void**)&cur2,  g_cur2);
    cudaGetSymbolAddress((void**)&csr1,  g_csr1);
    cudaGetSymbolAddress((void**)&csr2,  g_csr2);
    cudaGetSymbolAddress((void**)&part1, g_part1);
    cudaGetSymbolAddress((void**)&part2, g_part2);

    cudaFuncSetAttribute(mma_gemm_kernel, cudaFuncAttributeMaxDynamicSharedMemorySize, GSM_TOTAL);

    // --- bf16 splits ---
    split_kernel<<<ceil_div(Nn * IN_F / 4, 256), 256>>>(h, hhi, hlo, Nn * IN_F / 4);
    split_kernel<<<ceil_div(HD * IN_F / 4, 256), 256>>>(Wg1, wgh, wgl, HD * IN_F / 4);
    split_kernel<<<ceil_div(HD * IN_F / 4, 256), 256>>>(Wg2, wgh + HD * IN_F, wgl + HD * IN_F, HD * IN_F / 4);
    split_kernel<<<ceil_div(HD * HD2 / 4, 256), 256>>>(Wfc, wfch, wfcl, HD * HD2 / 4);

    // --- CSR build ---
    const int nb = ceil_div(Nn, 1024);
    zero_cnt_kernel<<<ceil_div(Nn, 256), 256>>>(Nn);
    hist_kernel<<<ceil_div(E1, 256), 256>>>(dst1, cnt1, E1);
    hist_kernel<<<ceil_div(E2, 256), 256>>>(dst2, cnt2, E2);
    partial_kernel<<<nb, 256>>>(cnt1, part1, Nn);
    partial_kernel<<<nb, 256>>>(cnt2, part2, Nn);
    top_scan_kernel<<<1, 32>>>(part1, nb);
    top_scan_kernel<<<1, 32>>>(part2, nb);
    final_scan_kernel<<<nb, 256>>>(cnt1, part1, off1, cur1, Nn, E1);
    final_scan_kernel<<<nb, 256>>>(cnt2, part2, off2, cur2, Nn, E2);
    fill_kernel<<<ceil_div(E1, 256), 256>>>(src1, dst1, cur1, csr1, E1);
    fill_kernel<<<ceil_div(E2, 256), 256>>>(src2, dst2, cur2, csr2, E2);

    // --- fused projection GEMM (both relations), el/er in epilogue ---
    {
        dim3 grid(4, ceil_div(Nn, 128));
        mma_gemm_kernel<<<grid, 256, GSM_TOTAL>>>(hhi, hlo, wgh, wgl, Nn, IN_F, 0,
                                                  nullptr, feat1, feat2,
                                                  al1, ar1, al2, ar2,
                                                  el1, er1, el2, er2, nullptr);
    }
    // --- fused softmax + aggregate (writes sem hi/lo with bias folded) ---
    {
        int grid = ceil_div(Nn * 32, 256);
        gat_aggregate_kernel<<<grid, 256>>>(off1, csr1, el1, er1, feat1, b1, 0,  Nn);
        gat_aggregate_kernel<<<grid, 256>>>(off2, csr2, el2, er2, feat2, b2, HD, Nn);
    }
    // --- FC GEMM ---
    {
        dim3 grid(2, ceil_div(Nn, 128));
        mma_gemm_kernel<<<grid, 256, GSM_TOTAL>>>(semh, seml, wfch, wfcl, Nn, HD2, 1,
                                                  out, nullptr, nullptr,
                                                  nullptr, nullptr, nullptr, nullptr,
                                                  nullptr, nullptr, nullptr, nullptr, bfc);
    }
}

// round 9
// speedup vs baseline: 6.2056x; 1.0881x over previous
#include <cuda_runtime.h>
#include <cuda_bf16.h>
#include <math.h>
#include <stdint.h>

#define NNODES 50000
#define EMAXE  800000
#define IN_F   256
#define HH     4
#define DD     64
#define HD     256
#define HD2    512
#define NEG_SLOPE 0.2f

// ---------------- scratch (static __device__, no allocs) ----------------
__device__ __align__(16) float g_feat1[NNODES * HD];
__device__ __align__(16) float g_feat2[NNODES * HD];
__device__ __align__(16) float g_el1[NNODES * HH], g_er1[NNODES * HH];
__device__ __align__(16) float g_el2[NNODES * HH], g_er2[NNODES * HH];

// bf16 split operands
__device__ __align__(16) __nv_bfloat16 g_h_hi[NNODES * IN_F],  g_h_lo[NNODES * IN_F];
__device__ __align__(16) __nv_bfloat16 g_semh[NNODES * HD2],   g_seml[NNODES * HD2];
__device__ __align__(16) __nv_bfloat16 g_wgh[HD2 * IN_F], g_wgl[HD2 * IN_F];   // Wg1 rows 0-255, Wg2 rows 256-511
__device__ __align__(16) __nv_bfloat16 g_wfch[HD * HD2],  g_wfcl[HD * HD2];

// CSR-by-dst scratch
__device__ int g_cnt1[NNODES],  g_cnt2[NNODES];
__device__ int g_off1[NNODES + 1], g_off2[NNODES + 1];
__device__ int g_cur1[NNODES],  g_cur2[NNODES];
__device__ int g_csr1[EMAXE],   g_csr2[EMAXE];
__device__ int g_part1[64],     g_part2[64];

// ================= helpers =================
__device__ __forceinline__ uint32_t smem_u32(const void* p) {
    uint32_t a;
    asm("{ .reg .u64 t; cvta.to.shared.u64 t, %1; cvt.u32.u64 %0, t; }" : "=r"(a) : "l"(p));
    return a;
}

#define LDSM_X4(r0, r1, r2, r3, addr) \
    asm volatile("ldmatrix.sync.aligned.m8n8.x4.shared.b16 {%0,%1,%2,%3}, [%4];" \
                 : "=r"(r0), "=r"(r1), "=r"(r2), "=r"(r3) : "r"(addr))

#define MMA_16816(d, a0, a1, a2, a3, b0, b1) \
    asm volatile("mma.sync.aligned.m16n8k16.row.col.f32.bf16.bf16.f32 " \
                 "{%0,%1,%2,%3}, {%4,%5,%6,%7}, {%8,%9}, {%0,%1,%2,%3};" \
                 : "+f"((d)[0]), "+f"((d)[1]), "+f"((d)[2]), "+f"((d)[3]) \
                 : "r"(a0), "r"(a1), "r"(a2), "r"(a3), "r"(b0), "r"(b1))

#define CP16(dst, src) \
    asm volatile("cp.async.cg.shared.global [%0], [%1], 16;" :: "r"(dst), "l"(src))
#define CP_COMMIT() asm volatile("cp.async.commit_group;" ::: "memory")
#define CP_WAIT1()  asm volatile("cp.async.wait_group 1;" ::: "memory")

// XOR swizzle for 64B rows (Swizzle<2,3,3>): byte offset within one 128x32bf16 tile.
// row in [0,128), cb = byte column in [0,64). 16B chunk index XORed with (row>>1)&3.
__device__ __forceinline__ uint32_t swz(uint32_t row, uint32_t cb) {
    return row * 64 + ((((cb >> 4) ^ ((row >> 1) & 3)) << 4) | (cb & 15));
}

// ================= fp32 -> bf16 hi/lo split =================
__global__ void split_kernel(const float* __restrict__ x,
                             __nv_bfloat16* __restrict__ hi,
                             __nv_bfloat16* __restrict__ lo, int n4)
{
    int i = blockIdx.x * blockDim.x + threadIdx.x;
    if (i >= n4) return;
    float4 v = ((const float4*)x)[i];
    float vv[4] = {v.x, v.y, v.z, v.w};
    __align__(8) __nv_bfloat16 hb[4], lb[4];
#pragma unroll
    for (int k = 0; k < 4; k++) {
        hb[k] = __float2bfloat16(vv[k]);
        lb[k] = __float2bfloat16(vv[k] - __bfloat162float(hb[k]));
    }
    ((uint2*)hi)[i] = *(uint2*)hb;
    ((uint2*)lo)[i] = *(uint2*)lb;
}

// ================= split-bf16 GEMM via mma.sync, cp.async 2-stage, swizzled =================
#define GK 32
#define TB 8192                      // one 128x32 bf16 tile (64B rows, swizzled)
#define STG (4 * TB)                 // Ah|Al|Bh|Bl per stage = 32KB
#define GSM_TOTAL (2 * STG)          // 64KB

__device__ __forceinline__ void load_chunk(uint32_t sbs,
    const __nv_bfloat16* __restrict__ Ah, const __nv_bfloat16* __restrict__ Al,
    const __nv_bfloat16* __restrict__ Bh, const __nv_bfloat16* __restrict__ Bl,
    int m0, int n0, int M, int K, int kc, int tid)
{
#pragma unroll
    for (int u = 0; u < 2; u++) {
        int c = tid * 2 + u;
        int row = c >> 2, cc = c & 3;
        uint32_t soff = swz((uint32_t)row, (uint32_t)cc * 16);
        int m = m0 + row;
        if (m < M) {
            size_t ga = (size_t)m * K + kc + cc * 8;
            CP16(sbs + soff,      (const char*)(Ah + ga));
            CP16(sbs + TB + soff, (const char*)(Al + ga));
        }
        size_t gb = (size_t)(n0 + row) * K + kc + cc * 8;
        CP16(sbs + 2 * TB + soff, (const char*)(Bh + gb));
        CP16(sbs + 3 * TB + soff, (const char*)(Bl + gb));
    }
}

__global__ void __launch_bounds__(256, 2)
mma_gemm_kernel(const __nv_bfloat16* __restrict__ Ah, const __nv_bfloat16* __restrict__ Al,
                const __nv_bfloat16* __restrict__ Bh, const __nv_bfloat16* __restrict__ Bl,
                int M, int K, int mode,
                float* __restrict__ C,
                float* __restrict__ feat1, float* __restrict__ feat2,
                const float* __restrict__ al1v, const float* __restrict__ ar1v,
                const float* __restrict__ al2v, const float* __restrict__ ar2v,
                float* __restrict__ el1, float* __restrict__ er1,
                float* __restrict__ el2, float* __restrict__ er2,
                const float* __restrict__ bias)
{
    extern __shared__ __align__(16) char dsm[];
    __shared__ float sAlv[128], sArv[128];
    __shared__ float sEl[256], sEr[256];

    const uint32_t sb = smem_u32(dsm);
    const int tid = threadIdx.x;
    const int lane = tid & 31;
    const int wid = tid >> 5;
    const int wm = wid >> 2;
    const int wn = wid & 3;
    const int m0 = blockIdx.y * 128, n0 = blockIdx.x * 128;

    const int rel = (n0 >= HD) ? 1 : 0;
    const int ncol0 = n0 & (HD - 1);
    const int h0 = ncol0 >> 6;

    if (mode == 0 && tid < 128) {
        const float* alsel = rel ? al2v : al1v;
        const float* arsel = rel ? ar2v : ar1v;
        sAlv[tid] = alsel[h0 * 64 + tid];
        sArv[tid] = arsel[h0 * 64 + tid];
    }
    sEl[tid] = 0.f; sEr[tid] = 0.f;

    float acc[4][4][4];
#pragma unroll
    for (int i = 0; i < 4; i++)
#pragma unroll
        for (int j = 0; j < 4; j++)
#pragma unroll
            for (int r = 0; r < 4; r++) acc[i][j][r] = 0.f;

    const int a_row = (lane & 15);
    const int a_kof = (lane >> 4) << 3;      // elements
    const int b_row = (lane & 7) + ((lane >> 4) << 3);
    const int b_kof = ((lane >> 3) & 1) << 3;

    const int nchunk = K / GK;
    load_chunk(sb, Ah, Al, Bh, Bl, m0, n0, M, K, 0, tid);
    CP_COMMIT();

    for (int c = 0; c < nchunk; c++) {
        if (c + 1 < nchunk)
            load_chunk(sb + ((c + 1) & 1) * STG, Ah, Al, Bh, Bl, m0, n0, M, K, (c + 1) * GK, tid);
        CP_COMMIT();
        CP_WAIT1();
        __syncthreads();

        const uint32_t sbs = sb + (c & 1) * STG;
        const uint32_t sbAh = sbs, sbAl = sbs + TB, sbBh = sbs + 2 * TB, sbBl = sbs + 3 * TB;
#pragma unroll
        for (int k0 = 0; k0 < GK; k0 += 16) {
            uint32_t bh[4][2], bl[4][2];
#pragma unroll
            for (int g = 0; g < 2; g++) {
                int nrow = wn * 32 + g * 16 + b_row;
                uint32_t ba = swz((uint32_t)nrow, (uint32_t)(k0 + b_kof) * 2);
                uint32_t r0, r1, r2, r3;
                LDSM_X4(r0, r1, r2, r3, sbBh + ba);
                bh[g * 2][0] = r0; bh[g * 2][1] = r1;
                bh[g * 2 + 1][0] = r2; bh[g * 2 + 1][1] = r3;
                LDSM_X4(r0, r1, r2, r3, sbBl + ba);
                bl[g * 2][0] = r0; bl[g * 2][1] = r1;
                bl[g * 2 + 1][0] = r2; bl[g * 2 + 1][1] = r3;
            }
#pragma unroll
            for (int im = 0; im < 4; im++) {
                int arow = wm * 64 + im * 16 + a_row;
                uint32_t aa = swz((uint32_t)arow, (uint32_t)(k0 + a_kof) * 2);
                uint32_t ah0, ah1, ah2, ah3, al0, al1, al2, al3;
                LDSM_X4(ah0, ah1, ah2, ah3, sbAh + aa);
                LDSM_X4(al0, al1, al2, al3, sbAl + aa);
#pragma unroll
                for (int in = 0; in < 4; in++) {
                    MMA_16816(acc[im][in], ah0, ah1, ah2, ah3, bh[in][0], bh[in][1]);
                    MMA_16816(acc[im][in], ah0, ah1, ah2, ah3, bl[in][0], bl[in][1]);
                    MMA_16816(acc[im][in], al0, al1, al2, al3, bh[in][0], bh[in][1]);
                }
            }
        }
        __syncthreads();
    }

    // ---- epilogue ----
    if (mode == 0) {
        float* Cf = rel ? feat2 : feat1;
        const int hl = wn >> 1;
#pragma unroll
        for (int im = 0; im < 4; im++) {
            int r0l = wm * 64 + im * 16 + (lane >> 2);
            float e0 = 0.f, e1 = 0.f, q0 = 0.f, q1 = 0.f;
#pragma unroll
            for (int in = 0; in < 4; in++) {
                int ct = wn * 32 + in * 8 + (lane & 3) * 2;
                float a0 = sAlv[ct], a1 = sAlv[ct + 1];
                float p0 = sArv[ct], p1 = sArv[ct + 1];
                e0 += acc[im][in][0] * a0 + acc[im][in][1] * a1;
                q0 += acc[im][in][0] * p0 + acc[im][in][1] * p1;
                e1 += acc[im][in][2] * a0 + acc[im][in][3] * a1;
                q1 += acc[im][in][2] * p0 + acc[im][in][3] * p1;

                int row0 = m0 + r0l;
                int col  = ncol0 + ct;
                if (row0 < M)
                    *(float2*)(Cf + (size_t)row0 * HD + col) =
                        make_float2(acc[im][in][0], acc[im][in][1]);
                if (row0 + 8 < M)
                    *(float2*)(Cf + (size_t)(row0 + 8) * HD + col) =
                        make_float2(acc[im][in][2], acc[im][in][3]);
            }
            atomicAdd(&sEl[r0l * 2 + hl], e0);
            atomicAdd(&sEr[r0l * 2 + hl], q0);
            atomicAdd(&sEl[(r0l + 8) * 2 + hl], e1);
            atomicAdd(&sEr[(r0l + 8) * 2 + hl], q1);
        }
        __syncthreads();
        if (tid < 128) {
            int m = m0 + tid;
            if (m < M) {
                float* elo = rel ? el2 : el1;
                float* ero = rel ? er2 : er1;
                elo[(size_t)m * HH + h0 + 0] = sEl[tid * 2 + 0];
                elo[(size_t)m * HH + h0 + 1] = sEl[tid * 2 + 1];
                ero[(size_t)m * HH + h0 + 0] = sEr[tid * 2 + 0];
                ero[(size_t)m * HH + h0 + 1] = sEr[tid * 2 + 1];
            }
        }
    } else {
#pragma unroll
        for (int im = 0; im < 4; im++) {
#pragma unroll
            for (int in = 0; in < 4; in++) {
                int row0 = m0 + wm * 64 + im * 16 + (lane >> 2);
                int col  = n0 + wn * 32 + in * 8 + (lane & 3) * 2;
                float bx = bias[col], by = bias[col + 1];
                if (row0 < M)
                    *(float2*)(C + (size_t)row0 * HD + col) =
                        make_float2(acc[im][in][0] + bx, acc[im][in][1] + by);
                if (row0 + 8 < M)
                    *(float2*)(C + (size_t)(row0 + 8) * HD + col) =
                        make_float2(acc[im][in][2] + bx, acc[im][in][3] + by);
            }
        }
    }
}

// ================= CSR build (merged: gridDim.y = relation) =================
__global__ void zero_cnt_kernel(int Nn)
{
    int i = blockIdx.x * blockDim.x + threadIdx.x;
    if (i < Nn) { g_cnt1[i] = 0; g_cnt2[i] = 0; }
}

__global__ void hist_kernel(const int* __restrict__ dst1, const int* __restrict__ dst2,
                            int E1, int E2)
{
    int e = blockIdx.x * blockDim.x + threadIdx.x;
    if (blockIdx.y == 0) { if (e < E1) atomicAdd(&g_cnt1[dst1[e]], 1); }
    else                 { if (e < E2) atomicAdd(&g_cnt2[dst2[e]], 1); }
}

__global__ void partial_kernel(int Nn)
{
    __shared__ int sred[256];
    const int* cnt = blockIdx.y ? g_cnt2 : g_cnt1;
    int* part = blockIdx.y ? g_part2 : g_part1;
    int tid = threadIdx.x;
    int base = blockIdx.x * 1024;
    int sum = 0;
#pragma unroll
    for (int j = 0; j < 4; j++) {
        int i = base + j * 256 + tid;
        if (i < Nn) sum += cnt[i];
    }
    sred[tid] = sum;
    __syncthreads();
#pragma unroll
    for (int o = 128; o; o >>= 1) {
        if (tid < o) sred[tid] += sred[tid + o];
        __syncthreads();
    }
    if (tid == 0) part[blockIdx.x] = sred[0];
}

__global__ void top_scan_kernel(int nb)
{
    int* part = blockIdx.x ? g_part2 : g_part1;
    if (threadIdx.x == 0) {
        int run = 0;
        for (int i = 0; i < nb; i++) { int v = part[i]; part[i] = run; run += v; }
    }
}

__global__ void final_scan_kernel(int Nn, int E1, int E2)
{
    __shared__ int s[256];
    const int* cnt = blockIdx.y ? g_cnt2 : g_cnt1;
    const int* part = blockIdx.y ? g_part2 : g_part1;
    int* off = blockIdx.y ? g_off2 : g_off1;
    int* cur = blockIdx.y ? g_cur2 : g_cur1;
    int E = blockIdx.y ? E2 : E1;
    int tid = threadIdx.x;
    int base = blockIdx.x * 1024;
    int v[4]; int loc = 0;
#pragma unroll
    for (int j = 0; j < 4; j++) {
        int i = base + tid * 4 + j;
        v[j] = (i < Nn) ? cnt[i] : 0;
        loc += v[j];
    }
    s[tid] = loc;
    __syncthreads();
#pragma unroll
    for (int o = 1; o < 256; o <<= 1) {
        int t = (tid >= o) ? s[tid - o] : 0;
        __syncthreads();
        s[tid] += t;
        __syncthreads();
    }
    int run = part[blockIdx.x] + s[tid] - loc;
#pragma unroll
    for (int j = 0; j < 4; j++) {
        int i = base + tid * 4 + j;
        if (i < Nn) { off[i] = run; cur[i] = run; run += v[j]; }
    }
    if (blockIdx.x == 0 && tid == 0) off[Nn] = E;
}

__global__ void fill_kernel(const int* __restrict__ src1, const int* __restrict__ dst1,
                            const int* __restrict__ src2, const int* __restrict__ dst2,
                            int E1, int E2)
{
    int e = blockIdx.x * blockDim.x + threadIdx.x;
    if (blockIdx.y == 0) {
        if (e < E1) { int pos = atomicAdd(&g_cur1[dst1[e]], 1); g_csr1[pos] = src1[e]; }
    } else {
        if (e < E2) { int pos = atomicAdd(&g_cur2[dst2[e]], 1); g_csr2[pos] = src2[e]; }
    }
}

// ================= fused GAT aggregate: warp per dst node, gridDim.y = relation ====
__global__ void gat_aggregate_kernel(const float* __restrict__ b1v,
                                     const float* __restrict__ b2v, int Nn)
{
    int n = (blockIdx.x * blockDim.x + threadIdx.x) >> 5;
    int lane = threadIdx.x & 31;
    if (n >= Nn) return;
    const int relv = blockIdx.y;
    const int* off = relv ? g_off2 : g_off1;
    const int* csr = relv ? g_csr2 : g_csr1;
    const float* el = relv ? g_el2 : g_el1;
    const float* er = relv ? g_er2 : g_er1;
    const float* feat = relv ? g_feat2 : g_feat1;
    const float* bias = relv ? b2v : b1v;
    const int rel_off = relv ? HD : 0;

    const int beg = off[n], end = off[n + 1];
    float4 er4 = *(const float4*)(er + n * HH);

    float4 m = make_float4(-INFINITY, -INFINITY, -INFINITY, -INFINITY);
    for (int k = beg + lane; k < end; k += 32) {
        int s = csr[k];
        float4 l = *(const float4*)(el + s * HH);
        float4 e;
        e.x = l.x + er4.x; e.x = e.x > 0.f ? e.x : NEG_SLOPE * e.x;
        e.y = l.y + er4.y; e.y = e.y > 0.f ? e.y : NEG_SLOPE * e.y;
        e.z = l.z + er4.z; e.z = e.z > 0.f ? e.z : NEG_SLOPE * e.z;
        e.w = l.w + er4.w; e.w = e.w > 0.f ? e.w : NEG_SLOPE * e.w;
        m.x = fmaxf(m.x, e.x); m.y = fmaxf(m.y, e.y);
        m.z = fmaxf(m.z, e.z); m.w = fmaxf(m.w, e.w);
    }
#pragma unroll
    for (int o = 16; o; o >>= 1) {
        m.x = fmaxf(m.x, __shfl_xor_sync(0xffffffffu, m.x, o));
        m.y = fmaxf(m.y, __shfl_xor_sync(0xffffffffu, m.y, o));
        m.z = fmaxf(m.z, __shfl_xor_sync(0xffffffffu, m.z, o));
        m.w = fmaxf(m.w, __shfl_xor_sync(0xffffffffu, m.w, o));
    }

    float4 ds = make_float4(0.f, 0.f, 0.f, 0.f);
    for (int k = beg + lane; k < end; k += 32) {
        int s = csr[k];
        float4 l = *(const float4*)(el + s * HH);
        float4 e;
        e.x = l.x + er4.x; e.x = e.x > 0.f ? e.x : NEG_SLOPE * e.x;
        e.y = l.y + er4.y; e.y = e.y > 0.f ? e.y : NEG_SLOPE * e.y;
        e.z = l.z + er4.z; e.z = e.z > 0.f ? e.z : NEG_SLOPE * e.z;
        e.w = l.w + er4.w; e.w = e.w > 0.f ? e.w : NEG_SLOPE * e.w;
        ds.x += __expf(e.x - m.x); ds.y += __expf(e.y - m.y);
        ds.z += __expf(e.z - m.z); ds.w += __expf(e.w - m.w);
    }
#pragma unroll
    for (int o = 16; o; o >>= 1) {
        ds.x += __shfl_xor_sync(0xffffffffu, ds.x, o);
        ds.y += __shfl_xor_sync(0xffffffffu, ds.y, o);
        ds.z += __shfl_xor_sync(0xffffffffu, ds.z, o);
        ds.w += __shfl_xor_sync(0xffffffffu, ds.w, o);
    }

    const int head = lane >> 3;
    const float mh   = head == 0 ? m.x  : head == 1 ? m.y  : head == 2 ? m.z  : m.w;
    const float dh   = head == 0 ? ds.x : head == 1 ? ds.y : head == 2 ? ds.z : ds.w;
    const float erh  = head == 0 ? er4.x: head == 1 ? er4.y: head == 2 ? er4.z: er4.w;
    const float invd = 1.0f / dh;

    float acc[8];
#pragma unroll
    for (int i = 0; i < 8; i++) acc[i] = 0.f;

    for (int base = beg; base < end; base += 32) {
        int myidx = (base + lane < end) ? csr[base + lane] : 0;
        int cnt = min(32, end - base);
#pragma unroll 2
        for (int j = 0; j < cnt; j++) {
            int s = __shfl_sync(0xffffffffu, myidx, j);
            float e = el[s * HH + head] + erh;
            e = e > 0.f ? e : NEG_SLOPE * e;
            float alpha = __expf(e - mh) * invd;
            const float4* fp = (const float4*)(feat + (size_t)s * HD + lane * 8);
            float4 a = fp[0], b = fp[1];
            acc[0] = fmaf(a.x, alpha, acc[0]);
            acc[1] = fmaf(a.y, alpha, acc[1]);
            acc[2] = fmaf(a.z, alpha, acc[2]);
            acc[3] = fmaf(a.w, alpha, acc[3]);
            acc[4] = fmaf(b.x, alpha, acc[4]);
            acc[5] = fmaf(b.y, alpha, acc[5]);
            acc[6] = fmaf(b.z, alpha, acc[6]);
            acc[7] = fmaf(b.w, alpha, acc[7]);
        }
    }

    float4 bo0 = *(const float4*)(bias + lane * 8);
    float4 bo1 = *(const float4*)(bias + lane * 8 + 4);
    float w[8];
    w[0] = acc[0] + bo0.x; w[1] = acc[1] + bo0.y; w[2] = acc[2] + bo0.z; w[3] = acc[3] + bo0.w;
    w[4] = acc[4] + bo1.x; w[5] = acc[5] + bo1.y; w[6] = acc[6] + bo1.z; w[7] = acc[7] + bo1.w;

    __align__(16) __nv_bfloat16 hb[8], lb[8];
#pragma unroll
    for (int i = 0; i < 8; i++) {
        hb[i] = __float2bfloat16(w[i]);
        lb[i] = __float2bfloat16(w[i] - __bfloat162float(hb[i]));
    }
    size_t didx = (size_t)n * HD2 + rel_off + lane * 8;
    *(uint4*)(g_semh + didx) = *(uint4*)hb;
    *(uint4*)(g_seml + didx) = *(uint4*)lb;
}

// ================= launch =================
static inline int ceil_div(int a, int b) { return (a + b - 1) / b; }

extern "C" void kernel_launch(void* const* d_in, const int* in_sizes, int n_in,
                              void* d_out, int out_size)
{
    const float* h    = (const float*)d_in[0];
    const float* Wg1  = (const float*)d_in[1];
    const float* al1  = (const float*)d_in[2];
    const float* ar1  = (const float*)d_in[3];
    const float* b1   = (const float*)d_in[4];
    const float* Wg2  = (const float*)d_in[5];
    const float* al2  = (const float*)d_in[6];
    const float* ar2  = (const float*)d_in[7];
    const float* b2   = (const float*)d_in[8];
    const float* Wfc  = (const float*)d_in[9];
    const float* bfc  = (const float*)d_in[10];
    const int*   src1 = (const int*)d_in[11];
    const int*   dst1 = (const int*)d_in[12];
    const int*   src2 = (const int*)d_in[13];
    const int*   dst2 = (const int*)d_in[14];
    float* out = (float*)d_out;

    const int Nn = in_sizes[0] / IN_F;
    const int E1 = in_sizes[11];
    const int E2 = in_sizes[13];

    float *feat1, *feat2, *el1, *er1, *el2, *er2;
    __nv_bfloat16 *hhi, *hlo, *semh, *seml, *wgh, *wgl, *wfch, *wfcl;
    cudaGetSymbolAddress((void**)&feat1, g_feat1);
    cudaGetSymbolAddress((void**)&feat2, g_feat2);
    cudaGetSymbolAddress((void**)&el1,   g_el1);
    cudaGetSymbolAddress((void**)&er1,   g_er1);
    cudaGetSymbolAddress((void**)&el2,   g_el2);
    cudaGetSymbolAddress((void**)&er2,   g_er2);
    cudaGetSymbolAddress((void**)&hhi,   g_h_hi);
    cudaGetSymbolAddress((void**)&hlo,   g_h_lo);
    cudaGetSymbolAddress((void**)&semh,  g_semh);
    cudaGetSymbolAddress((void**)&seml,  g_seml);
    cudaGetSymbolAddress((void**)&wgh,   g_wgh);
    cudaGetSymbolAddress((void**)&wgl,   g_wgl);
    cudaGetSymbolAddress((void**)&wfch,  g_wfch);
    cudaGetSymbolAddress((void**)&wfcl,  g_wfcl);

    cudaFuncSetAttribute(mma_gemm_kernel, cudaFuncAttributeMaxDynamicSharedMemorySize, GSM_TOTAL);

    // --- bf16 splits ---
    split_kernel<<<ceil_div(Nn * IN_F / 4, 256), 256>>>(h, hhi, hlo, Nn * IN_F / 4);
    split_kernel<<<ceil_div(HD * IN_F / 4, 256), 256>>>(Wg1, wgh, wgl, HD * IN_F / 4);
    split_kernel<<<ceil_div(HD * IN_F / 4, 256), 256>>>(Wg2, wgh + HD * IN_F, wgl + HD * IN_F, HD * IN_F / 4);
    split_kernel<<<ceil_div(HD * HD2 / 4, 256), 256>>>(Wfc, wfch, wfcl, HD * HD2 / 4);

    // --- CSR build (merged launches) ---
    const int nb = ceil_div(Nn, 1024);
    const int Emax = E1 > E2 ? E1 : E2;
    zero_cnt_kernel<<<ceil_div(Nn, 256), 256>>>(Nn);
    {
        dim3 g(ceil_div(Emax, 256), 2);
        hist_kernel<<<g, 256>>>(dst1, dst2, E1, E2);
    }
    {
        dim3 g(nb, 2);
        partial_kernel<<<g, 256>>>(Nn);
        top_scan_kernel<<<2, 32>>>(nb);
        final_scan_kernel<<<g, 256>>>(Nn, E1, E2);
    }
    {
        dim3 g(ceil_div(Emax, 256), 2);
        fill_kernel<<<g, 256>>>(src1, dst1, src2, dst2, E1, E2);
    }

    // --- fused projection GEMM (both relations), el/er in epilogue ---
    {
        dim3 grid(4, ceil_div(Nn, 128));
        mma_gemm_kernel<<<grid, 256, GSM_TOTAL>>>(hhi, hlo, wgh, wgl, Nn, IN_F, 0,
                                                  nullptr, feat1, feat2,
                                                  al1, ar1, al2, ar2,
                                                  el1, er1, el2, er2, nullptr);
    }
    // --- fused softmax + aggregate (both relations, writes sem hi/lo, bias folded) ---
    {
        dim3 grid(ceil_div(Nn * 32, 256), 2);
        gat_aggregate_kernel<<<grid, 256>>>(b1, b2, Nn);
    }
    // --- FC GEMM ---
    {
        dim3 grid(2, ceil_div(Nn, 128));
        mma_gemm_kernel<<<grid, 256, GSM_TOTAL>>>(semh, seml, wfch, wfcl, Nn, HD2, 1,
                                                  out, nullptr, nullptr,
                                                  nullptr, nullptr, nullptr, nullptr,
                                                  nullptr, nullptr, nullptr, nullptr, bfc);
    }
}

// round 10
// speedup vs baseline: 6.6696x; 1.0748x over previous
#include <cuda_runtime.h>
#include <cuda_bf16.h>
#include <cuda_fp16.h>
#include <math.h>
#include <stdint.h>

#define NNODES 50000
#define EMAXE  800000
#define IN_F   256
#define HH     4
#define DD     64
#define HD     256
#define HD2    512
#define NEG_SLOPE 0.2f

// ---------------- scratch (static __device__, no allocs) ----------------
__device__ __align__(16) __half g_feat1[NNODES * HD];     // fp16 feat (aggregate-only consumer)
__device__ __align__(16) __half g_feat2[NNODES * HD];
__device__ __align__(16) float g_el1[NNODES * HH], g_er1[NNODES * HH];
__device__ __align__(16) float g_el2[NNODES * HH], g_er2[NNODES * HH];

// bf16 split operands
__device__ __align__(16) __nv_bfloat16 g_h_hi[NNODES * IN_F],  g_h_lo[NNODES * IN_F];
__device__ __align__(16) __nv_bfloat16 g_semh[NNODES * HD2],   g_seml[NNODES * HD2];
__device__ __align__(16) __nv_bfloat16 g_wgh[HD2 * IN_F], g_wgl[HD2 * IN_F];   // Wg1 rows 0-255, Wg2 rows 256-511
__device__ __align__(16) __nv_bfloat16 g_wfch[HD * HD2],  g_wfcl[HD * HD2];

// CSR-by-dst scratch
__device__ int g_cnt1[NNODES],  g_cnt2[NNODES];
__device__ int g_off1[NNODES + 1], g_off2[NNODES + 1];
__device__ int g_cur1[NNODES],  g_cur2[NNODES];
__device__ int g_csr1[EMAXE],   g_csr2[EMAXE];
__device__ int g_part1[64],     g_part2[64];

// ================= helpers =================
__device__ __forceinline__ uint32_t smem_u32(const void* p) {
    uint32_t a;
    asm("{ .reg .u64 t; cvta.to.shared.u64 t, %1; cvt.u32.u64 %0, t; }" : "=r"(a) : "l"(p));
    return a;
}

#define LDSM_X4(r0, r1, r2, r3, addr) \
    asm volatile("ldmatrix.sync.aligned.m8n8.x4.shared.b16 {%0,%1,%2,%3}, [%4];" \
                 : "=r"(r0), "=r"(r1), "=r"(r2), "=r"(r3) : "r"(addr))

#define MMA_16816(d, a0, a1, a2, a3, b0, b1) \
    asm volatile("mma.sync.aligned.m16n8k16.row.col.f32.bf16.bf16.f32 " \
                 "{%0,%1,%2,%3}, {%4,%5,%6,%7}, {%8,%9}, {%0,%1,%2,%3};" \
                 : "+f"((d)[0]), "+f"((d)[1]), "+f"((d)[2]), "+f"((d)[3]) \
                 : "r"(a0), "r"(a1), "r"(a2), "r"(a3), "r"(b0), "r"(b1))

#define CP16(dst, src) \
    asm volatile("cp.async.cg.shared.global [%0], [%1], 16;" :: "r"(dst), "l"(src))
#define CP_COMMIT() asm volatile("cp.async.commit_group;" ::: "memory")
#define CP_WAIT1()  asm volatile("cp.async.wait_group 1;" ::: "memory")

// XOR swizzle for 64B rows: byte offset within one 128x32bf16 tile.
__device__ __forceinline__ uint32_t swz(uint32_t row, uint32_t cb) {
    return row * 64 + ((((cb >> 4) ^ ((row >> 1) & 3)) << 4) | (cb & 15));
}

// ================= fp32 -> bf16 hi/lo split =================
__global__ void split_kernel(const float* __restrict__ x,
                             __nv_bfloat16* __restrict__ hi,
                             __nv_bfloat16* __restrict__ lo, int n4)
{
    int i = blockIdx.x * blockDim.x + threadIdx.x;
    if (i >= n4) return;
    float4 v = ((const float4*)x)[i];
    float vv[4] = {v.x, v.y, v.z, v.w};
    __align__(8) __nv_bfloat16 hb[4], lb[4];
#pragma unroll
    for (int k = 0; k < 4; k++) {
        hb[k] = __float2bfloat16(vv[k]);
        lb[k] = __float2bfloat16(vv[k] - __bfloat162float(hb[k]));
    }
    ((uint2*)hi)[i] = *(uint2*)hb;
    ((uint2*)lo)[i] = *(uint2*)lb;
}

// ================= split-bf16 GEMM via mma.sync, cp.async 2-stage, swizzled =================
#define GK 32
#define TB 8192
#define STG (4 * TB)
#define GSM_TOTAL (2 * STG)

__device__ __forceinline__ void load_chunk(uint32_t sbs,
    const __nv_bfloat16* __restrict__ Ah, const __nv_bfloat16* __restrict__ Al,
    const __nv_bfloat16* __restrict__ Bh, const __nv_bfloat16* __restrict__ Bl,
    int m0, int n0, int M, int K, int kc, int tid)
{
#pragma unroll
    for (int u = 0; u < 2; u++) {
        int c = tid * 2 + u;
        int row = c >> 2, cc = c & 3;
        uint32_t soff = swz((uint32_t)row, (uint32_t)cc * 16);
        int m = m0 + row;
        if (m < M) {
            size_t ga = (size_t)m * K + kc + cc * 8;
            CP16(sbs + soff,      (const char*)(Ah + ga));
            CP16(sbs + TB + soff, (const char*)(Al + ga));
        }
        size_t gb = (size_t)(n0 + row) * K + kc + cc * 8;
        CP16(sbs + 2 * TB + soff, (const char*)(Bh + gb));
        CP16(sbs + 3 * TB + soff, (const char*)(Bl + gb));
    }
}

__global__ void __launch_bounds__(256, 2)
mma_gemm_kernel(const __nv_bfloat16* __restrict__ Ah, const __nv_bfloat16* __restrict__ Al,
                const __nv_bfloat16* __restrict__ Bh, const __nv_bfloat16* __restrict__ Bl,
                int M, int K, int mode,
                float* __restrict__ C,
                __half* __restrict__ feat1, __half* __restrict__ feat2,
                const float* __restrict__ al1v, const float* __restrict__ ar1v,
                const float* __restrict__ al2v, const float* __restrict__ ar2v,
                float* __restrict__ el1, float* __restrict__ er1,
                float* __restrict__ el2, float* __restrict__ er2,
                const float* __restrict__ bias)
{
    extern __shared__ __align__(16) char dsm[];
    __shared__ float sAlv[128], sArv[128];
    __shared__ float sEl[256], sEr[256];

    const uint32_t sb = smem_u32(dsm);
    const int tid = threadIdx.x;
    const int lane = tid & 31;
    const int wid = tid >> 5;
    const int wm = wid >> 2;
    const int wn = wid & 3;
    const int m0 = blockIdx.y * 128, n0 = blockIdx.x * 128;

    const int rel = (n0 >= HD) ? 1 : 0;
    const int ncol0 = n0 & (HD - 1);
    const int h0 = ncol0 >> 6;

    if (mode == 0 && tid < 128) {
        const float* alsel = rel ? al2v : al1v;
        const float* arsel = rel ? ar2v : ar1v;
        sAlv[tid] = alsel[h0 * 64 + tid];
        sArv[tid] = arsel[h0 * 64 + tid];
    }
    sEl[tid] = 0.f; sEr[tid] = 0.f;

    float acc[4][4][4];
#pragma unroll
    for (int i = 0; i < 4; i++)
#pragma unroll
        for (int j = 0; j < 4; j++)
#pragma unroll
            for (int r = 0; r < 4; r++) acc[i][j][r] = 0.f;

    const int a_row = (lane & 15);
    const int a_kof = (lane >> 4) << 3;
    const int b_row = (lane & 7) + ((lane >> 4) << 3);
    const int b_kof = ((lane >> 3) & 1) << 3;

    const int nchunk = K / GK;
    load_chunk(sb, Ah, Al, Bh, Bl, m0, n0, M, K, 0, tid);
    CP_COMMIT();

    for (int c = 0; c < nchunk; c++) {
        if (c + 1 < nchunk)
            load_chunk(sb + ((c + 1) & 1) * STG, Ah, Al, Bh, Bl, m0, n0, M, K, (c + 1) * GK, tid);
        CP_COMMIT();
        CP_WAIT1();
        __syncthreads();

        const uint32_t sbs = sb + (c & 1) * STG;
        const uint32_t sbAh = sbs, sbAl = sbs + TB, sbBh = sbs + 2 * TB, sbBl = sbs + 3 * TB;
#pragma unroll
        for (int k0 = 0; k0 < GK; k0 += 16) {
            uint32_t bh[4][2], bl[4][2];
#pragma unroll
            for (int g = 0; g < 2; g++) {
                int nrow = wn * 32 + g * 16 + b_row;
                uint32_t ba = swz((uint32_t)nrow, (uint32_t)(k0 + b_kof) * 2);
                uint32_t r0, r1, r2, r3;
                LDSM_X4(r0, r1, r2, r3, sbBh + ba);
                bh[g * 2][0] = r0; bh[g * 2][1] = r1;
                bh[g * 2 + 1][0] = r2; bh[g * 2 + 1][1] = r3;
                LDSM_X4(r0, r1, r2, r3, sbBl + ba);
                bl[g * 2][0] = r0; bl[g * 2][1] = r1;
                bl[g * 2 + 1][0] = r2; bl[g * 2 + 1][1] = r3;
            }
#pragma unroll
            for (int im = 0; im < 4; im++) {
                int arow = wm * 64 + im * 16 + a_row;
                uint32_t aa = swz((uint32_t)arow, (uint32_t)(k0 + a_kof) * 2);
                uint32_t ah0, ah1, ah2, ah3, al0, al1, al2, al3;
                LDSM_X4(ah0, ah1, ah2, ah3, sbAh + aa);
                LDSM_X4(al0, al1, al2, al3, sbAl + aa);
#pragma unroll
                for (int in = 0; in < 4; in++) {
                    MMA_16816(acc[im][in], ah0, ah1, ah2, ah3, bh[in][0], bh[in][1]);
                    MMA_16816(acc[im][in], ah0, ah1, ah2, ah3, bl[in][0], bl[in][1]);
                    MMA_16816(acc[im][in], al0, al1, al2, al3, bh[in][0], bh[in][1]);
                }
            }
        }
        __syncthreads();
    }

    // ---- epilogue ----
    if (mode == 0) {
        __half* Cf = rel ? feat2 : feat1;
        const int hl = wn >> 1;
#pragma unroll
        for (int im = 0; im < 4; im++) {
            int r0l = wm * 64 + im * 16 + (lane >> 2);
            float e0 = 0.f, e1 = 0.f, q0 = 0.f, q1 = 0.f;
#pragma unroll
            for (int in = 0; in < 4; in++) {
                int ct = wn * 32 + in * 8 + (lane & 3) * 2;
                float a0 = sAlv[ct], a1 = sAlv[ct + 1];
                float p0 = sArv[ct], p1 = sArv[ct + 1];
                e0 += acc[im][in][0] * a0 + acc[im][in][1] * a1;
                q0 += acc[im][in][0] * p0 + acc[im][in][1] * p1;
                e1 += acc[im][in][2] * a0 + acc[im][in][3] * a1;
                q1 += acc[im][in][2] * p0 + acc[im][in][3] * p1;

                int row0 = m0 + r0l;
                int col  = ncol0 + ct;
                if (row0 < M)
                    *(__half2*)(Cf + (size_t)row0 * HD + col) =
                        __floats2half2_rn(acc[im][in][0], acc[im][in][1]);
                if (row0 + 8 < M)
                    *(__half2*)(Cf + (size_t)(row0 + 8) * HD + col) =
                        __floats2half2_rn(acc[im][in][2], acc[im][in][3]);
            }
            atomicAdd(&sEl[r0l * 2 + hl], e0);
            atomicAdd(&sEr[r0l * 2 + hl], q0);
            atomicAdd(&sEl[(r0l + 8) * 2 + hl], e1);
            atomicAdd(&sEr[(r0l + 8) * 2 + hl], q1);
        }
        __syncthreads();
        if (tid < 128) {
            int m = m0 + tid;
            if (m < M) {
                float* elo = rel ? el2 : el1;
                float* ero = rel ? er2 : er1;
                elo[(size_t)m * HH + h0 + 0] = sEl[tid * 2 + 0];
                elo[(size_t)m * HH + h0 + 1] = sEl[tid * 2 + 1];
                ero[(size_t)m * HH + h0 + 0] = sEr[tid * 2 + 0];
                ero[(size_t)m * HH + h0 + 1] = sEr[tid * 2 + 1];
            }
        }
    } else {
#pragma unroll
        for (int im = 0; im < 4; im++) {
#pragma unroll
            for (int in = 0; in < 4; in++) {
                int row0 = m0 + wm * 64 + im * 16 + (lane >> 2);
                int col  = n0 + wn * 32 + in * 8 + (lane & 3) * 2;
                float bx = bias[col], by = bias[col + 1];
                if (row0 < M)
                    *(float2*)(C + (size_t)row0 * HD + col) =
                        make_float2(acc[im][in][0] + bx, acc[im][in][1] + by);
                if (row0 + 8 < M)
                    *(float2*)(C + (size_t)(row0 + 8) * HD + col) =
                        make_float2(acc[im][in][2] + bx, acc[im][in][3] + by);
            }
        }
    }
}

// ================= CSR build (merged: gridDim.y = relation) =================
__global__ void zero_cnt_kernel(int Nn)
{
    int i = blockIdx.x * blockDim.x + threadIdx.x;
    if (i < Nn) { g_cnt1[i] = 0; g_cnt2[i] = 0; }
}

__global__ void hist_kernel(const int* __restrict__ dst1, const int* __restrict__ dst2,
                            int E1, int E2)
{
    int e = blockIdx.x * blockDim.x + threadIdx.x;
    if (blockIdx.y == 0) { if (e < E1) atomicAdd(&g_cnt1[dst1[e]], 1); }
    else                 { if (e < E2) atomicAdd(&g_cnt2[dst2[e]], 1); }
}

__global__ void partial_kernel(int Nn)
{
    __shared__ int sred[256];
    const int* cnt = blockIdx.y ? g_cnt2 : g_cnt1;
    int* part = blockIdx.y ? g_part2 : g_part1;
    int tid = threadIdx.x;
    int base = blockIdx.x * 1024;
    int sum = 0;
#pragma unroll
    for (int j = 0; j < 4; j++) {
        int i = base + j * 256 + tid;
        if (i < Nn) sum += cnt[i];
    }
    sred[tid] = sum;
    __syncthreads();
#pragma unroll
    for (int o = 128; o; o >>= 1) {
        if (tid < o) sred[tid] += sred[tid + o];
        __syncthreads();
    }
    if (tid == 0) part[blockIdx.x] = sred[0];
}

__global__ void top_scan_kernel(int nb)
{
    int* part = blockIdx.x ? g_part2 : g_part1;
    if (threadIdx.x == 0) {
        int run = 0;
        for (int i = 0; i < nb; i++) { int v = part[i]; part[i] = run; run += v; }
    }
}

__global__ void final_scan_kernel(int Nn, int E1, int E2)
{
    __shared__ int s[256];
    const int* cnt = blockIdx.y ? g_cnt2 : g_cnt1;
    const int* part = blockIdx.y ? g_part2 : g_part1;
    int* off = blockIdx.y ? g_off2 : g_off1;
    int* cur = blockIdx.y ? g_cur2 : g_cur1;
    int E = blockIdx.y ? E2 : E1;
    int tid = threadIdx.x;
    int base = blockIdx.x * 1024;
    int v[4]; int loc = 0;
#pragma unroll
    for (int j = 0; j < 4; j++) {
        int i = base + tid * 4 + j;
        v[j] = (i < Nn) ? cnt[i] : 0;
        loc += v[j];
    }
    s[tid] = loc;
    __syncthreads();
#pragma unroll
    for (int o = 1; o < 256; o <<= 1) {
        int t = (tid >= o) ? s[tid - o] : 0;
        __syncthreads();
        s[tid] += t;
        __syncthreads();
    }
    int run = part[blockIdx.x] + s[tid] - loc;
#pragma unroll
    for (int j = 0; j < 4; j++) {
        int i = base + tid * 4 + j;
        if (i < Nn) { off[i] = run; cur[i] = run; run += v[j]; }
    }
    if (blockIdx.x == 0 && tid == 0) off[Nn] = E;
}

__global__ void fill_kernel(const int* __restrict__ src1, const int* __restrict__ dst1,
                            const int* __restrict__ src2, const int* __restrict__ dst2,
                            int E1, int E2)
{
    int e = blockIdx.x * blockDim.x + threadIdx.x;
    if (blockIdx.y == 0) {
        if (e < E1) { int pos = atomicAdd(&g_cur1[dst1[e]], 1); g_csr1[pos] = src1[e]; }
    } else {
        if (e < E2) { int pos = atomicAdd(&g_cur2[dst2[e]], 1); g_csr2[pos] = src2[e]; }
    }
}

// ================= fused GAT aggregate: warp per dst node, 2 passes, fp16 gather ====
__global__ void gat_aggregate_kernel(const float* __restrict__ b1v,
                                     const float* __restrict__ b2v, int Nn)
{
    int n = (blockIdx.x * blockDim.x + threadIdx.x) >> 5;
    int lane = threadIdx.x & 31;
    if (n >= Nn) return;
    const int relv = blockIdx.y;
    const int* off = relv ? g_off2 : g_off1;
    const int* csr = relv ? g_csr2 : g_csr1;
    const float* el = relv ? g_el2 : g_el1;
    const float* er = relv ? g_er2 : g_er1;
    const __half* feat = relv ? g_feat2 : g_feat1;
    const float* bias = relv ? b2v : b1v;
    const int rel_off = relv ? HD : 0;

    const int beg = off[n], end = off[n + 1];
    float4 er4 = *(const float4*)(er + n * HH);

    // pass 1: denom (no max subtraction; |e| is small so exp is safe)
    float4 ds = make_float4(0.f, 0.f, 0.f, 0.f);
    for (int k = beg + lane; k < end; k += 32) {
        int s = csr[k];
        float4 l = *(const float4*)(el + s * HH);
        float4 e;
        e.x = l.x + er4.x; e.x = e.x > 0.f ? e.x : NEG_SLOPE * e.x;
        e.y = l.y + er4.y; e.y = e.y > 0.f ? e.y : NEG_SLOPE * e.y;
        e.z = l.z + er4.z; e.z = e.z > 0.f ? e.z : NEG_SLOPE * e.z;
        e.w = l.w + er4.w; e.w = e.w > 0.f ? e.w : NEG_SLOPE * e.w;
        ds.x += __expf(e.x); ds.y += __expf(e.y);
        ds.z += __expf(e.z); ds.w += __expf(e.w);
    }
#pragma unroll
    for (int o = 16; o; o >>= 1) {
        ds.x += __shfl_xor_sync(0xffffffffu, ds.x, o);
        ds.y += __shfl_xor_sync(0xffffffffu, ds.y, o);
        ds.z += __shfl_xor_sync(0xffffffffu, ds.z, o);
        ds.w += __shfl_xor_sync(0xffffffffu, ds.w, o);
    }

    const int head = lane >> 3;
    const float dh   = head == 0 ? ds.x : head == 1 ? ds.y : head == 2 ? ds.z : ds.w;
    const float erh  = head == 0 ? er4.x: head == 1 ? er4.y: head == 2 ? er4.z: er4.w;
    const float invd = 1.0f / dh;

    float acc[8];
#pragma unroll
    for (int i = 0; i < 8; i++) acc[i] = 0.f;

    // pass 2: weighted fp16 gather. lane covers cols [lane*8, lane*8+8), head = lane>>3
    for (int base = beg; base < end; base += 32) {
        int myidx = (base + lane < end) ? csr[base + lane] : 0;
        int cnt = min(32, end - base);
#pragma unroll 2
        for (int j = 0; j < cnt; j++) {
            int s = __shfl_sync(0xffffffffu, myidx, j);
            float e = el[s * HH + head] + erh;
            e = e > 0.f ? e : NEG_SLOPE * e;
            float alpha = __expf(e) * invd;
            uint4 raw = *(const uint4*)(feat + (size_t)s * HD + lane * 8);
            float2 f0 = __half22float2(*(__half2*)&raw.x);
            float2 f1 = __half22float2(*(__half2*)&raw.y);
            float2 f2 = __half22float2(*(__half2*)&raw.z);
            float2 f3 = __half22float2(*(__half2*)&raw.w);
            acc[0] = fmaf(f0.x, alpha, acc[0]);
            acc[1] = fmaf(f0.y, alpha, acc[1]);
            acc[2] = fmaf(f1.x, alpha, acc[2]);
            acc[3] = fmaf(f1.y, alpha, acc[3]);
            acc[4] = fmaf(f2.x, alpha, acc[4]);
            acc[5] = fmaf(f2.y, alpha, acc[5]);
            acc[6] = fmaf(f3.x, alpha, acc[6]);
            acc[7] = fmaf(f3.y, alpha, acc[7]);
        }
    }

    float4 bo0 = *(const float4*)(bias + lane * 8);
    float4 bo1 = *(const float4*)(bias + lane * 8 + 4);
    float w[8];
    w[0] = acc[0] + bo0.x; w[1] = acc[1] + bo0.y; w[2] = acc[2] + bo0.z; w[3] = acc[3] + bo0.w;
    w[4] = acc[4] + bo1.x; w[5] = acc[5] + bo1.y; w[6] = acc[6] + bo1.z; w[7] = acc[7] + bo1.w;

    __align__(16) __nv_bfloat16 hb[8], lb[8];
#pragma unroll
    for (int i = 0; i < 8; i++) {
        hb[i] = __float2bfloat16(w[i]);
        lb[i] = __float2bfloat16(w[i] - __bfloat162float(hb[i]));
    }
    size_t didx = (size_t)n * HD2 + rel_off + lane * 8;
    *(uint4*)(g_semh + didx) = *(uint4*)hb;
    *(uint4*)(g_seml + didx) = *(uint4*)lb;
}

// ================= launch =================
static inline int ceil_div(int a, int b) { return (a + b - 1) / b; }

extern "C" void kernel_launch(void* const* d_in, const int* in_sizes, int n_in,
                              void* d_out, int out_size)
{
    const float* h    = (const float*)d_in[0];
    const float* Wg1  = (const float*)d_in[1];
    const float* al1  = (const float*)d_in[2];
    const float* ar1  = (const float*)d_in[3];
    const float* b1   = (const float*)d_in[4];
    const float* Wg2  = (const float*)d_in[5];
    const float* al2  = (const float*)d_in[6];
    const float* ar2  = (const float*)d_in[7];
    const float* b2   = (const float*)d_in[8];
    const float* Wfc  = (const float*)d_in[9];
    const float* bfc  = (const float*)d_in[10];
    const int*   src1 = (const int*)d_in[11];
    const int*   dst1 = (const int*)d_in[12];
    const int*   src2 = (const int*)d_in[13];
    const int*   dst2 = (const int*)d_in[14];
    float* out = (float*)d_out;

    const int Nn = in_sizes[0] / IN_F;
    const int E1 = in_sizes[11];
    const int E2 = in_sizes[13];

    __half *feat1, *feat2;
    float *el1, *er1, *el2, *er2;
    __nv_bfloat16 *hhi, *hlo, *semh, *seml, *wgh, *wgl, *wfch, *wfcl;
    cudaGetSymbolAddress((void**)&feat1, g_feat1);
    cudaGetSymbolAddress((void**)&feat2, g_feat2);
    cudaGetSymbolAddress((void**)&el1,   g_el1);
    cudaGetSymbolAddress((void**)&er1,   g_er1);
    cudaGetSymbolAddress((void**)&el2,   g_el2);
    cudaGetSymbolAddress((void**)&er2,   g_er2);
    cudaGetSymbolAddress((void**)&hhi,   g_h_hi);
    cudaGetSymbolAddress((void**)&hlo,   g_h_lo);
    cudaGetSymbolAddress((void**)&semh,  g_semh);
    cudaGetSymbolAddress((void**)&seml,  g_seml);
    cudaGetSymbolAddress((void**)&wgh,   g_wgh);
    cudaGetSymbolAddress((void**)&wgl,   g_wgl);
    cudaGetSymbolAddress((void**)&wfch,  g_wfch);
    cudaGetSymbolAddress((void**)&wfcl,  g_wfcl);

    cudaFuncSetAttribute(mma_gemm_kernel, cudaFuncAttributeMaxDynamicSharedMemorySize, GSM_TOTAL);

    // --- bf16 splits ---
    split_kernel<<<ceil_div(Nn * IN_F / 4, 256), 256>>>(h, hhi, hlo, Nn * IN_F / 4);
    split_kernel<<<ceil_div(HD * IN_F / 4, 256), 256>>>(Wg1, wgh, wgl, HD * IN_F / 4);
    split_kernel<<<ceil_div(HD * IN_F / 4, 256), 256>>>(Wg2, wgh + HD * IN_F, wgl + HD * IN_F, HD * IN_F / 4);
    split_kernel<<<ceil_div(HD * HD2 / 4, 256), 256>>>(Wfc, wfch, wfcl, HD * HD2 / 4);

    // --- CSR build (merged launches) ---
    const int nb = ceil_div(Nn, 1024);
    const int Emax = E1 > E2 ? E1 : E2;
    zero_cnt_kernel<<<ceil_div(Nn, 256), 256>>>(Nn);
    {
        dim3 g(ceil_div(Emax, 256), 2);
        hist_kernel<<<g, 256>>>(dst1, dst2, E1, E2);
    }
    {
        dim3 g(nb, 2);
        partial_kernel<<<g, 256>>>(Nn);
        top_scan_kernel<<<2, 32>>>(nb);
        final_scan_kernel<<<g, 256>>>(Nn, E1, E2);
    }
    {
        dim3 g(ceil_div(Emax, 256), 2);
        fill_kernel<<<g, 256>>>(src1, dst1, src2, dst2, E1, E2);
    }

    // --- fused projection GEMM (both relations), el/er in epilogue, fp16 feat out ---
    {
        dim3 grid(4, ceil_div(Nn, 128));
        mma_gemm_kernel<<<grid, 256, GSM_TOTAL>>>(hhi, hlo, wgh, wgl, Nn, IN_F, 0,
                                                  nullptr, feat1, feat2,
                                                  al1, ar1, al2, ar2,
                                                  el1, er1, el2, er2, nullptr);
    }
    // --- fused softmax + aggregate (both relations, fp16 gather, writes sem hi/lo) ---
    {
        dim3 grid(ceil_div(Nn * 32, 256), 2);
        gat_aggregate_kernel<<<grid, 256>>>(b1, b2, Nn);
    }
    // --- FC GEMM ---
    {
        dim3 grid(2, ceil_div(Nn, 128));
        mma_gemm_kernel<<<grid, 256, GSM_TOTAL>>>(semh, seml, wfch, wfcl, Nn, HD2, 1,
                                                  out, nullptr, nullptr,
                                                  nullptr, nullptr, nullptr, nullptr,
                                                  nullptr, nullptr, nullptr, nullptr, bfc);
    }
}